// round 8
// baseline (speedup 1.0000x reference)
#include <cuda_runtime.h>
#include <cuda_bf16.h>
#include <cstdint>
#include <cstddef>
#include <math.h>

#define T    60
#define NN   10000
#define EE   160000
#define INC  64
#define CAP  64
#define TOT  (T * NN)
#define TILES ((TOT + 127) / 128)

// ---------------- scratch ----------------
__device__ int      g_deg [TOT];
__device__ int      g_slot[(size_t)TOT * CAP];
__device__ uint32_t g_ah[(size_t)TOT * 64];   // bf16x2 rows: [mean(0..63)|x(64..127)] hi
__device__ uint32_t g_al[(size_t)TOT * 64];   // residual lo
__device__ float    g_p   [(size_t)TOT * 8];
__device__ float    g_rr  [(size_t)TOT * 8];
__device__ unsigned g_zenc[T * 8];

__device__ __forceinline__ unsigned encf(float f) {
    unsigned u = __float_as_uint(f);
    return (u & 0x80000000u) ? ~u : (u | 0x80000000u);
}
__device__ __forceinline__ float decf(unsigned u) {
    return (u & 0x80000000u) ? __uint_as_float(u & 0x7fffffffu) : __uint_as_float(~u);
}

// ---------------- K0: init ----------------
__global__ void k0_init() {
    int idx = blockIdx.x * blockDim.x + threadIdx.x;
    if (idx < TOT) g_deg[idx] = 0;
    if (idx < T * 8) g_zenc[idx] = 0u;
}

// ---------------- K1: single-pass bucketed CSR build (8 edges/thread) ----------------
__global__ void k1_build(const int* __restrict__ ei) {
    int q = blockIdx.x * blockDim.x + threadIdx.x;
    if (q >= T * (EE / 8)) return;
    int t = q / (EE / 8);
    int e = (q - t * (EE / 8)) * 8;
    const int* sp = ei + (size_t)t * 2 * EE + e;
    int4 sva = *(const int4*)sp;
    int4 svb = *(const int4*)(sp + 4);
    int4 dva = *(const int4*)(sp + EE);
    int4 dvb = *(const int4*)(sp + EE + 4);
    int tb = t * NN;
    int d0 = tb + dva.x, d1 = tb + dva.y, d2 = tb + dva.z, d3 = tb + dva.w;
    int d4 = tb + dvb.x, d5 = tb + dvb.y, d6 = tb + dvb.z, d7 = tb + dvb.w;
    int p0 = atomicAdd(&g_deg[d0], 1);
    int p1 = atomicAdd(&g_deg[d1], 1);
    int p2 = atomicAdd(&g_deg[d2], 1);
    int p3 = atomicAdd(&g_deg[d3], 1);
    int p4 = atomicAdd(&g_deg[d4], 1);
    int p5 = atomicAdd(&g_deg[d5], 1);
    int p6 = atomicAdd(&g_deg[d6], 1);
    int p7 = atomicAdd(&g_deg[d7], 1);
    if (p0 < CAP) g_slot[(size_t)d0 * CAP + p0] = sva.x;
    if (p1 < CAP) g_slot[(size_t)d1 * CAP + p1] = sva.y;
    if (p2 < CAP) g_slot[(size_t)d2 * CAP + p2] = sva.z;
    if (p3 < CAP) g_slot[(size_t)d3 * CAP + p3] = sva.w;
    if (p4 < CAP) g_slot[(size_t)d4 * CAP + p4] = svb.x;
    if (p5 < CAP) g_slot[(size_t)d5 * CAP + p5] = svb.y;
    if (p6 < CAP) g_slot[(size_t)d6 * CAP + p6] = svb.z;
    if (p7 < CAP) g_slot[(size_t)d7 * CAP + p7] = svb.w;
}

// ---------------- bf16 split helpers ----------------
__device__ __forceinline__ void split2(float a, float b, uint32_t& hi, uint32_t& lo) {
    __nv_bfloat162 h = __floats2bfloat162_rn(a, b);
    float ra = a - __bfloat162float(h.x);
    float rb = b - __bfloat162float(h.y);
    __nv_bfloat162 l = __floats2bfloat162_rn(ra, rb);
    hi = *(uint32_t*)&h;
    lo = *(uint32_t*)&l;
}

// ---------------- K4a: mean aggregation + split-bf16 A-row emit (warp/node) ----------------
__global__ void k4a_agg(const float* __restrict__ x) {
    int w = (blockIdx.x * blockDim.x + threadIdx.x) >> 5;
    int lane = threadIdx.x & 31;
    if (w >= TOT) return;
    int node = w;
    int t = node / NN;
    int deg = g_deg[node];
    int m = min(deg, CAP);
    const int* elist = g_slot + (size_t)node * CAP;
    const float* xt = x + (size_t)t * NN * INC;
    float sx = 0.f, sy = 0.f;
    int e = 0;
    for (; e + 8 <= m; e += 8) {
        int s0 = elist[e+0], s1 = elist[e+1], s2 = elist[e+2], s3 = elist[e+3];
        int s4 = elist[e+4], s5 = elist[e+5], s6 = elist[e+6], s7 = elist[e+7];
        float2 v0 = ((const float2*)(xt + (size_t)s0 * INC))[lane];
        float2 v1 = ((const float2*)(xt + (size_t)s1 * INC))[lane];
        float2 v2 = ((const float2*)(xt + (size_t)s2 * INC))[lane];
        float2 v3 = ((const float2*)(xt + (size_t)s3 * INC))[lane];
        float2 v4 = ((const float2*)(xt + (size_t)s4 * INC))[lane];
        float2 v5 = ((const float2*)(xt + (size_t)s5 * INC))[lane];
        float2 v6 = ((const float2*)(xt + (size_t)s6 * INC))[lane];
        float2 v7 = ((const float2*)(xt + (size_t)s7 * INC))[lane];
        sx += ((v0.x + v1.x) + (v2.x + v3.x)) + ((v4.x + v5.x) + (v6.x + v7.x));
        sy += ((v0.y + v1.y) + (v2.y + v3.y)) + ((v4.y + v5.y) + (v6.y + v7.y));
    }
    for (; e < m; e++) {
        int s0 = elist[e];
        float2 v0 = ((const float2*)(xt + (size_t)s0 * INC))[lane];
        sx += v0.x; sy += v0.y;
    }
    float inv = 1.0f / (float)max(deg, 1);
    uint32_t hi, lo;
    split2(sx * inv, sy * inv, hi, lo);
    g_ah[(size_t)node * 64 + lane] = hi;
    g_al[(size_t)node * 64 + lane] = lo;
    float2 xv = ((const float2*)(x + (size_t)node * INC))[lane];
    split2(xv.x, xv.y, hi, lo);
    g_ah[(size_t)node * 64 + 32 + lane] = hi;
    g_al[(size_t)node * 64 + 32 + lane] = lo;
}

// ---------------- mma / ldmatrix / cp.async helpers ----------------
__device__ __forceinline__ void mma16816(float* c,
    uint32_t a0, uint32_t a1, uint32_t a2, uint32_t a3, uint32_t b0, uint32_t b1)
{
    asm volatile(
        "mma.sync.aligned.m16n8k16.row.col.f32.bf16.bf16.f32 "
        "{%0,%1,%2,%3}, {%4,%5,%6,%7}, {%8,%9}, {%0,%1,%2,%3};"
        : "+f"(c[0]), "+f"(c[1]), "+f"(c[2]), "+f"(c[3])
        : "r"(a0), "r"(a1), "r"(a2), "r"(a3), "r"(b0), "r"(b1));
}
__device__ __forceinline__ void ldm_x4(uint32_t& r0, uint32_t& r1, uint32_t& r2, uint32_t& r3, uint32_t a) {
    asm volatile("ldmatrix.sync.aligned.m8n8.x4.shared.b16 {%0,%1,%2,%3}, [%4];"
        : "=r"(r0), "=r"(r1), "=r"(r2), "=r"(r3) : "r"(a));
}
__device__ __forceinline__ void ldm_x2(uint32_t& r0, uint32_t& r1, uint32_t a) {
    asm volatile("ldmatrix.sync.aligned.m8n8.x2.shared.b16 {%0,%1}, [%2];"
        : "=r"(r0), "=r"(r1) : "r"(a));
}
__device__ __forceinline__ void cpa16(uint32_t dst, const void* src) {
    asm volatile("cp.async.cg.shared.global [%0], [%1], 16;" :: "r"(dst), "l"(src) : "memory");
}
#define CPA_COMMIT() asm volatile("cp.async.commit_group;" ::: "memory")
#define CPA_WAIT1()  asm volatile("cp.async.wait_group 1;" ::: "memory")
__device__ __forceinline__ uint32_t smem_to_u32(const void* p) {
    uint32_t a;
    asm("{ .reg .u64 t; cvta.to.shared.u64 t, %1; cvt.u32.u64 %0, t; }" : "=r"(a) : "l"(p));
    return a;
}

// smem layout (bytes); padded A rows: 272 B (conflict-free ldmatrix)
#define KPB    272
#define ABUF(b) ((b) * 69632)          // each buf: hi @ +0 (34816), lo @ +34816
#define S_SAC2 139264                  // [8 warps][128 rows][20 floats] = 81920
#define S_W2T  221184                  // [128 cols][12] f32 = 6144
#define S_TOTAL 227328

// ---------------- K5: HMMA split GEMM, reg-resident B, cp.async pipelined A ----------------
__global__ __launch_bounds__(256) void k5_mma(
    const float* __restrict__ W1l, const float* __restrict__ W1r,
    const float* __restrict__ b1,
    const float* __restrict__ W2l, const float* __restrict__ W2r)
{
    extern __shared__ __align__(16) char smem[];
    uint32_t sbu = smem_to_u32(smem);
    int tid = threadIdx.x, wid = tid >> 5, lane = tid & 31;
    int gidq = lane >> 2, tig = lane & 3;

    // ---- stage B split into ABUF0 regions (temporary) + W2T ----
    for (int idx = tid; idx < 128 * 128; idx += 256) {
        int n = idx >> 7, k = idx & 127;
        float w = (k < 64) ? W1l[n * 64 + k] : W1r[n * 64 + (k - 64)];
        __nv_bfloat16 h = __float2bfloat16(w);
        __nv_bfloat16 l = __float2bfloat16(w - __bfloat162float(h));
        *(__nv_bfloat16*)(smem + n * KPB + k * 2) = h;
        *(__nv_bfloat16*)(smem + 34816 + n * KPB + k * 2) = l;
    }
    for (int idx = tid; idx < 128 * 12; idx += 256) {
        int c = idx / 12, j = idx % 12;
        float w = (j < 6) ? W2l[j * 128 + c] : W2r[(j - 6) * 128 + c];
        *(float*)(smem + S_W2T + (size_t)(c * 12 + j) * 4) = w;
    }
    __syncthreads();

    // ---- hoist this warp's B fragments (n-slice = wid*16 .. +16) ----
    uint32_t bh0[8][2], bh1[8][2], bl0[8][2], bl1[8][2];
    {
        int lsel = lane & 15;
        int nr = (lsel & 7);
        int kb8 = ((lsel >> 3) & 1) * 16;
#pragma unroll
        for (int ks = 0; ks < 8; ks++)
#pragma unroll
            for (int nt = 0; nt < 2; nt++) {
                uint32_t addr = sbu + (uint32_t)((wid * 16 + nt * 8 + nr) * KPB + ks * 32 + kb8);
                ldm_x2(bh0[ks][nt], bh1[ks][nt], addr);
                ldm_x2(bl0[ks][nt], bl1[ks][nt], addr + 34816);
            }
    }
    float b1g[2][2];
#pragma unroll
    for (int nt = 0; nt < 2; nt++)
#pragma unroll
        for (int e = 0; e < 2; e++)
            b1g[nt][e] = b1[wid * 16 + nt * 8 + tig * 2 + e];
    __syncthreads();   // all frags read before cp.async overwrites ABUF0

    // ---- A staging lambda (cp.async 16B chunks into padded rows) ----
    auto stageA = [&](int tileIdx, int buf) {
        int tb = min(tileIdx, TILES - 1) * 128;
        for (int c = tid; c < 2048; c += 256) {
            int row = c >> 4, wi = c & 15;
            int node = min(tb + row, TOT - 1);
            uint32_t dst = sbu + ABUF(buf) + row * KPB + wi * 16;
            cpa16(dst, g_ah + (size_t)node * 64 + wi * 4);
            cpa16(dst + 34816, g_al + (size_t)node * 64 + wi * 4);
        }
        CPA_COMMIT();
    };

    stageA(blockIdx.x, 0);
    int buf = 0;

    for (int tile = blockIdx.x; tile < TILES; tile += gridDim.x) {
        stageA(tile + gridDim.x, buf ^ 1);
        CPA_WAIT1();
        __syncthreads();

        // ---- compute ----
        float acc[8][2][4];
#pragma unroll
        for (int mb = 0; mb < 8; mb++)
#pragma unroll
            for (int nt = 0; nt < 2; nt++)
#pragma unroll
                for (int e = 0; e < 4; e++) acc[mb][nt][e] = 0.f;

        int arow_l = (lane & 7) + ((lane >> 3) & 1) * 8;
        int akb_l = (lane >> 4) * 16;
#pragma unroll
        for (int mb = 0; mb < 8; mb++) {
#pragma unroll
            for (int ks = 0; ks < 8; ks++) {
                uint32_t abase = sbu + ABUF(buf) + (uint32_t)((mb * 16 + arow_l) * KPB + ks * 32 + akb_l);
                uint32_t a0, a1, a2, a3, c0, c1, c2, c3;
                ldm_x4(a0, a1, a2, a3, abase);
                ldm_x4(c0, c1, c2, c3, abase + 34816);
#pragma unroll
                for (int nt = 0; nt < 2; nt++) {
                    mma16816(acc[mb][nt], a0, a1, a2, a3, bh0[ks][nt], bh1[ks][nt]);
                    mma16816(acc[mb][nt], a0, a1, a2, a3, bl0[ks][nt], bl1[ks][nt]);
                    mma16816(acc[mb][nt], c0, c1, c2, c3, bh0[ks][nt], bh1[ks][nt]);
                }
            }
        }

        // ---- epilogue: bias+relu + W2 projection, per-warp slab STS ----
#pragma unroll
        for (int mb = 0; mb < 8; mb++) {
            float p0[12], p1[12];
#pragma unroll
            for (int j = 0; j < 12; j++) { p0[j] = 0.f; p1[j] = 0.f; }
#pragma unroll
            for (int nt = 0; nt < 2; nt++)
#pragma unroll
                for (int e = 0; e < 2; e++) {
                    float bb = b1g[nt][e];
                    float h0 = fmaxf(acc[mb][nt][e] + bb, 0.f);
                    float h1 = fmaxf(acc[mb][nt][2 + e] + bb, 0.f);
                    int col = wid * 16 + nt * 8 + tig * 2 + e;
                    const float* wv = (const float*)(smem + S_W2T) + col * 12;
                    float4 w0 = *(const float4*)wv;
                    float4 w1 = *(const float4*)(wv + 4);
                    float4 w2 = *(const float4*)(wv + 8);
                    p0[0] += h0 * w0.x; p0[1] += h0 * w0.y; p0[2] += h0 * w0.z; p0[3] += h0 * w0.w;
                    p0[4] += h0 * w1.x; p0[5] += h0 * w1.y; p0[6] += h0 * w1.z; p0[7] += h0 * w1.w;
                    p0[8] += h0 * w2.x; p0[9] += h0 * w2.y; p0[10] += h0 * w2.z; p0[11] += h0 * w2.w;
                    p1[0] += h1 * w0.x; p1[1] += h1 * w0.y; p1[2] += h1 * w0.z; p1[3] += h1 * w0.w;
                    p1[4] += h1 * w1.x; p1[5] += h1 * w1.y; p1[6] += h1 * w1.z; p1[7] += h1 * w1.w;
                    p1[8] += h1 * w2.x; p1[9] += h1 * w2.y; p1[10] += h1 * w2.z; p1[11] += h1 * w2.w;
                }
#pragma unroll
            for (int o = 1; o <= 2; o <<= 1)
#pragma unroll
                for (int j = 0; j < 12; j++) {
                    p0[j] += __shfl_xor_sync(0xffffffffu, p0[j], o);
                    p1[j] += __shfl_xor_sync(0xffffffffu, p1[j], o);
                }
            if (tig == 0) {
                float* s0 = (float*)(smem + S_SAC2) + (size_t)(wid * 128 + mb * 16 + gidq) * 20;
                *(float4*)s0 = make_float4(p0[0], p0[1], p0[2], p0[3]);
                *(float4*)(s0 + 4) = make_float4(p0[4], p0[5], p0[6], p0[7]);
                *(float4*)(s0 + 8) = make_float4(p0[8], p0[9], p0[10], p0[11]);
                float* s1 = s0 + 8 * 20;
                *(float4*)s1 = make_float4(p1[0], p1[1], p1[2], p1[3]);
                *(float4*)(s1 + 4) = make_float4(p1[4], p1[5], p1[6], p1[7]);
                *(float4*)(s1 + 8) = make_float4(p1[8], p1[9], p1[10], p1[11]);
            }
        }
        __syncthreads();

        // ---- cross-warp reduce + writeout (threads 0..127 = rows) ----
        if (tid < 128) {
            int node = tile * 128 + tid;
            if (node < TOT) {
                float s[12];
#pragma unroll
                for (int j = 0; j < 12; j++) s[j] = 0.f;
#pragma unroll
                for (int w2 = 0; w2 < 8; w2++) {
                    const float* p = (const float*)(smem + S_SAC2) + (size_t)(w2 * 128 + tid) * 20;
                    float4 a = *(const float4*)p;
                    float4 b = *(const float4*)(p + 4);
                    float4 c = *(const float4*)(p + 8);
                    s[0] += a.x; s[1] += a.y; s[2] += a.z; s[3] += a.w;
                    s[4] += b.x; s[5] += b.y; s[6] += b.z; s[7] += b.w;
                    s[8] += c.x; s[9] += c.y; s[10] += c.z; s[11] += c.w;
                }
                float* gp = g_p + (size_t)node * 8;
                *(float4*)gp = make_float4(s[0], s[1], s[2], s[3]);
                *(float2*)(gp + 4) = make_float2(s[4], s[5]);
                float* gr = g_rr + (size_t)node * 8;
                *(float4*)gr = make_float4(s[6], s[7], s[8], s[9]);
                *(float2*)(gr + 4) = make_float2(s[10], s[11]);
            }
        }
        __syncthreads();
        buf ^= 1;
    }
}

// ---------------- K6: layer-2 aggregation + global max pool ----------------
#define K6_CHUNKS 157
__global__ void k6_layer2(const float* __restrict__ b2) {
    int t = blockIdx.x / K6_CHUNKS;
    int chunk = blockIdx.x % K6_CHUNKS;
    int i = chunk * 64 + (threadIdx.x >> 2);
    int q = threadIdx.x & 3;
    __shared__ unsigned zmax[6];
    if (threadIdx.x < 6) zmax[threadIdx.x] = 0u;
    __syncthreads();
    if (i < NN) {
        int node = t * NN + i;
        int deg = g_deg[node];
        int m = min(deg, CAP);
        const int* elist = g_slot + (size_t)node * CAP;
        int tb = t * NN;
        float s0 = 0, s1 = 0, s2 = 0, s3 = 0, s4 = 0, s5 = 0;
        for (int e = q; e < m; e += 4) {
            const float4* pp = (const float4*)(g_p + (size_t)(tb + elist[e]) * 8);
            float4 a = pp[0];
            float4 b = pp[1];
            s0 += a.x; s1 += a.y; s2 += a.z; s3 += a.w; s4 += b.x; s5 += b.y;
        }
#pragma unroll
        for (int o = 1; o <= 2; o <<= 1) {
            s0 += __shfl_xor_sync(0xffffffffu, s0, o);
            s1 += __shfl_xor_sync(0xffffffffu, s1, o);
            s2 += __shfl_xor_sync(0xffffffffu, s2, o);
            s3 += __shfl_xor_sync(0xffffffffu, s3, o);
            s4 += __shfl_xor_sync(0xffffffffu, s4, o);
            s5 += __shfl_xor_sync(0xffffffffu, s5, o);
        }
        if (q == 0) {
            float inv = 1.0f / (float)max(deg, 1);
            size_t base = (size_t)node * 8;
            atomicMax(&zmax[0], encf(s0 * inv + b2[0] + g_rr[base + 0]));
            atomicMax(&zmax[1], encf(s1 * inv + b2[1] + g_rr[base + 1]));
            atomicMax(&zmax[2], encf(s2 * inv + b2[2] + g_rr[base + 2]));
            atomicMax(&zmax[3], encf(s3 * inv + b2[3] + g_rr[base + 3]));
            atomicMax(&zmax[4], encf(s4 * inv + b2[4] + g_rr[base + 4]));
            atomicMax(&zmax[5], encf(s5 * inv + b2[5] + g_rr[base + 5]));
        }
    }
    __syncthreads();
    if (threadIdx.x < 6) atomicMax(&g_zenc[t * 8 + threadIdx.x], zmax[threadIdx.x]);
}

// ---------------- K7: GRU + NCE + outputs ----------------
__global__ void k7_final(const float* __restrict__ wih,
                         const float* __restrict__ bih,
                         const float* __restrict__ bhh,
                         float* __restrict__ out, int out_size)
{
    __shared__ float z[T * 6];
    __shared__ float gout[30 * 6];
    __shared__ float redf[256];
    __shared__ int   redi[256];
    int tid = threadIdx.x;
    for (int idx = tid; idx < T * 6; idx += 256)
        z[idx] = decf(g_zenc[(idx / 6) * 8 + (idx % 6)]);
    __syncthreads();
    if (tid < 180) {
        int t = tid / 6, j = tid % 6;
        float ar = 0.f, au = 0.f, an = 0.f;
#pragma unroll
        for (int d = 0; d < 6; d++) {
            float zv = z[t * 6 + d];
            ar += zv * wih[(0 + j) * 6 + d];
            au += zv * wih[(6 + j) * 6 + d];
            an += zv * wih[(12 + j) * 6 + d];
        }
        float r = 1.f / (1.f + expf(-(ar + bih[j]      + bhh[j])));
        float u = 1.f / (1.f + expf(-(au + bih[6 + j]  + bhh[6 + j])));
        float n = tanhf(an + bih[12 + j] + r * bhh[12 + j]);
        gout[tid] = (1.f - u) * n;
    }
    __syncthreads();
    float lnce = 0.f; int lc = 0;
    if (tid < 240) {
        int tp = tid / 12;
        int ii = tid % 12 + 1;
        int t = 10 + tp;
        const int joff[8] = {0, 11, 12, 13, 14, 15, 16, 17};
        float lg[8];
#pragma unroll
        for (int s = 0; s < 8; s++) {
            int idx = t + ii + joff[s];
            float d = 0.f;
#pragma unroll
            for (int c = 0; c < 6; c++) d += z[idx * 6 + c] * gout[t * 6 + c];
            lg[s] = d;
        }
        float m = lg[0];
#pragma unroll
        for (int s = 1; s < 8; s++) m = fmaxf(m, lg[s]);
        float se = 0.f;
#pragma unroll
        for (int s = 0; s < 8; s++) se += expf(lg[s] - m);
        lnce = lg[0] - m - logf(se);
        bool ok = true;
#pragma unroll
        for (int s = 1; s < 8; s++) if (lg[s] > lg[0]) ok = false;
        lc = ok ? 1 : 0;
    }
    redf[tid] = lnce; redi[tid] = lc;
    __syncthreads();
    for (int o = 128; o > 0; o >>= 1) {
        if (tid < o) { redf[tid] += redf[tid + o]; redi[tid] += redi[tid + o]; }
        __syncthreads();
    }
    if (tid == 0) {
        if (out_size > 0) out[0] = redf[0] / (-240.0f);
        if (out_size > 1) out[1] = (float)redi[0] / 240.0f;
    }
    if (tid < 180 && (2 + tid) < out_size) out[2 + tid] = gout[tid];
    for (int idx = 182 + tid; idx < out_size; idx += 256) out[idx] = 0.f;
}

// ---------------- launch ----------------
extern "C" void kernel_launch(void* const* d_in, const int* in_sizes, int n_in,
                              void* d_out, int out_size)
{
    const float* x   = (const float*)d_in[0];
    const int*   ei  = (const int*)  d_in[1];
    const float* W1l = (const float*)d_in[2];
    const float* W1r = (const float*)d_in[3];
    const float* b1  = (const float*)d_in[4];
    const float* W2l = (const float*)d_in[5];
    const float* W2r = (const float*)d_in[6];
    const float* b2  = (const float*)d_in[7];
    const float* wih = (const float*)d_in[8];
    const float* bih = (const float*)d_in[10];
    const float* bhh = (const float*)d_in[11];
    float* out = (float*)d_out;

    cudaFuncSetAttribute(k5_mma, cudaFuncAttributeMaxDynamicSharedMemorySize, S_TOTAL);

    k0_init <<<(TOT + 255) / 256, 256>>>();
    k1_build<<<(T * (EE / 8) + 255) / 256, 256>>>(ei);
    k4a_agg <<<(TOT * 32 + 255) / 256, 256>>>(x);
    k5_mma  <<<148, 256, S_TOTAL>>>(W1l, W1r, b1, W2l, W2r);
    k6_layer2<<<T * K6_CHUNKS, 256>>>(b2);
    k7_final<<<1, 256>>>(wih, bih, bhh, out, out_size);
}

// round 9
// speedup vs baseline: 1.0004x; 1.0004x over previous
#include <cuda_runtime.h>
#include <cuda_bf16.h>
#include <cstdint>
#include <cstddef>
#include <math.h>

#define T    60
#define NN   10000
#define EE   160000
#define INC  64
#define CAP  64
#define TOT  (T * NN)
#define TILES ((TOT + 127) / 128)

// ---------------- scratch ----------------
__device__ int      g_deg [TOT];
__device__ int      g_slot[(size_t)TOT * CAP];
__device__ uint32_t g_ah[(size_t)TOT * 64];   // bf16x2 rows: [mean(0..63)|x(64..127)] hi
__device__ uint32_t g_al[(size_t)TOT * 64];   // residual lo
__device__ float    g_p   [(size_t)TOT * 8];
__device__ float    g_rr  [(size_t)TOT * 8];
__device__ unsigned g_zenc[T * 8];

__device__ __forceinline__ unsigned encf(float f) {
    unsigned u = __float_as_uint(f);
    return (u & 0x80000000u) ? ~u : (u | 0x80000000u);
}
__device__ __forceinline__ float decf(unsigned u) {
    return (u & 0x80000000u) ? __uint_as_float(u & 0x7fffffffu) : __uint_as_float(~u);
}

// ---------------- K0: init ----------------
__global__ void k0_init() {
    int idx = blockIdx.x * blockDim.x + threadIdx.x;
    if (idx < TOT) g_deg[idx] = 0;
    if (idx < T * 8) g_zenc[idx] = 0u;
}

// ---------------- K1: single-pass bucketed CSR build (8 edges/thread) ----------------
__global__ void k1_build(const int* __restrict__ ei) {
    int q = blockIdx.x * blockDim.x + threadIdx.x;
    if (q >= T * (EE / 8)) return;
    int t = q / (EE / 8);
    int e = (q - t * (EE / 8)) * 8;
    const int* sp = ei + (size_t)t * 2 * EE + e;
    int4 sva = *(const int4*)sp;
    int4 svb = *(const int4*)(sp + 4);
    int4 dva = *(const int4*)(sp + EE);
    int4 dvb = *(const int4*)(sp + EE + 4);
    int tb = t * NN;
    int d0 = tb + dva.x, d1 = tb + dva.y, d2 = tb + dva.z, d3 = tb + dva.w;
    int d4 = tb + dvb.x, d5 = tb + dvb.y, d6 = tb + dvb.z, d7 = tb + dvb.w;
    int p0 = atomicAdd(&g_deg[d0], 1);
    int p1 = atomicAdd(&g_deg[d1], 1);
    int p2 = atomicAdd(&g_deg[d2], 1);
    int p3 = atomicAdd(&g_deg[d3], 1);
    int p4 = atomicAdd(&g_deg[d4], 1);
    int p5 = atomicAdd(&g_deg[d5], 1);
    int p6 = atomicAdd(&g_deg[d6], 1);
    int p7 = atomicAdd(&g_deg[d7], 1);
    if (p0 < CAP) g_slot[(size_t)d0 * CAP + p0] = sva.x;
    if (p1 < CAP) g_slot[(size_t)d1 * CAP + p1] = sva.y;
    if (p2 < CAP) g_slot[(size_t)d2 * CAP + p2] = sva.z;
    if (p3 < CAP) g_slot[(size_t)d3 * CAP + p3] = sva.w;
    if (p4 < CAP) g_slot[(size_t)d4 * CAP + p4] = svb.x;
    if (p5 < CAP) g_slot[(size_t)d5 * CAP + p5] = svb.y;
    if (p6 < CAP) g_slot[(size_t)d6 * CAP + p6] = svb.z;
    if (p7 < CAP) g_slot[(size_t)d7 * CAP + p7] = svb.w;
}

// ---------------- bf16 split helpers ----------------
__device__ __forceinline__ void split2(float a, float b, uint32_t& hi, uint32_t& lo) {
    __nv_bfloat162 h = __floats2bfloat162_rn(a, b);
    float ra = a - __bfloat162float(h.x);
    float rb = b - __bfloat162float(h.y);
    __nv_bfloat162 l = __floats2bfloat162_rn(ra, rb);
    hi = *(uint32_t*)&h;
    lo = *(uint32_t*)&l;
}

// ---------------- K4a: mean aggregation + split-bf16 A-row emit (warp/node) ----------------
__global__ void k4a_agg(const float* __restrict__ x) {
    int w = (blockIdx.x * blockDim.x + threadIdx.x) >> 5;
    int lane = threadIdx.x & 31;
    if (w >= TOT) return;
    int node = w;
    int t = node / NN;
    int deg = g_deg[node];
    int m = min(deg, CAP);
    const int* elist = g_slot + (size_t)node * CAP;
    const float* xt = x + (size_t)t * NN * INC;
    float sx = 0.f, sy = 0.f;
    int e = 0;
    for (; e + 8 <= m; e += 8) {
        int s0 = elist[e+0], s1 = elist[e+1], s2 = elist[e+2], s3 = elist[e+3];
        int s4 = elist[e+4], s5 = elist[e+5], s6 = elist[e+6], s7 = elist[e+7];
        float2 v0 = ((const float2*)(xt + (size_t)s0 * INC))[lane];
        float2 v1 = ((const float2*)(xt + (size_t)s1 * INC))[lane];
        float2 v2 = ((const float2*)(xt + (size_t)s2 * INC))[lane];
        float2 v3 = ((const float2*)(xt + (size_t)s3 * INC))[lane];
        float2 v4 = ((const float2*)(xt + (size_t)s4 * INC))[lane];
        float2 v5 = ((const float2*)(xt + (size_t)s5 * INC))[lane];
        float2 v6 = ((const float2*)(xt + (size_t)s6 * INC))[lane];
        float2 v7 = ((const float2*)(xt + (size_t)s7 * INC))[lane];
        sx += ((v0.x + v1.x) + (v2.x + v3.x)) + ((v4.x + v5.x) + (v6.x + v7.x));
        sy += ((v0.y + v1.y) + (v2.y + v3.y)) + ((v4.y + v5.y) + (v6.y + v7.y));
    }
    for (; e < m; e++) {
        int s0 = elist[e];
        float2 v0 = ((const float2*)(xt + (size_t)s0 * INC))[lane];
        sx += v0.x; sy += v0.y;
    }
    float inv = 1.0f / (float)max(deg, 1);
    uint32_t hi, lo;
    split2(sx * inv, sy * inv, hi, lo);
    g_ah[(size_t)node * 64 + lane] = hi;
    g_al[(size_t)node * 64 + lane] = lo;
    float2 xv = ((const float2*)(x + (size_t)node * INC))[lane];
    split2(xv.x, xv.y, hi, lo);
    g_ah[(size_t)node * 64 + 32 + lane] = hi;
    g_al[(size_t)node * 64 + 32 + lane] = lo;
}

// ---------------- mma / ldmatrix / cp.async helpers ----------------
__device__ __forceinline__ void mma16816(float* c,
    uint32_t a0, uint32_t a1, uint32_t a2, uint32_t a3, uint32_t b0, uint32_t b1)
{
    asm volatile(
        "mma.sync.aligned.m16n8k16.row.col.f32.bf16.bf16.f32 "
        "{%0,%1,%2,%3}, {%4,%5,%6,%7}, {%8,%9}, {%0,%1,%2,%3};"
        : "+f"(c[0]), "+f"(c[1]), "+f"(c[2]), "+f"(c[3])
        : "r"(a0), "r"(a1), "r"(a2), "r"(a3), "r"(b0), "r"(b1));
}
__device__ __forceinline__ void ldm_x4(uint32_t& r0, uint32_t& r1, uint32_t& r2, uint32_t& r3, uint32_t a) {
    asm volatile("ldmatrix.sync.aligned.m8n8.x4.shared.b16 {%0,%1,%2,%3}, [%4];"
        : "=r"(r0), "=r"(r1), "=r"(r2), "=r"(r3) : "r"(a));
}
__device__ __forceinline__ void ldm_x2(uint32_t& r0, uint32_t& r1, uint32_t a) {
    asm volatile("ldmatrix.sync.aligned.m8n8.x2.shared.b16 {%0,%1}, [%2];"
        : "=r"(r0), "=r"(r1) : "r"(a));
}
__device__ __forceinline__ void cpa16(uint32_t dst, const void* src) {
    asm volatile("cp.async.cg.shared.global [%0], [%1], 16;" :: "r"(dst), "l"(src) : "memory");
}
#define CPA_COMMIT() asm volatile("cp.async.commit_group;" ::: "memory")
#define CPA_WAIT1()  asm volatile("cp.async.wait_group 1;" ::: "memory")
__device__ __forceinline__ uint32_t smem_to_u32(const void* p) {
    uint32_t a;
    asm("{ .reg .u64 t; cvta.to.shared.u64 t, %1; cvt.u32.u64 %0, t; }" : "=r"(a) : "l"(p));
    return a;
}

// smem layout (bytes); padded A rows: 272 B (conflict-free ldmatrix)
#define KPB    272
#define ABUF(b) ((b) * 69632)          // each buf: hi @ +0 (34816), lo @ +34816
#define S_SAC2 139264                  // [8 warps][128 rows][20 floats] = 81920
#define S_W2T  221184                  // [128 cols][12] f32 = 6144
#define S_TOTAL 227328

// ---------------- K5: HMMA split GEMM, 6 independent MMA chains / warp ----------------
__global__ __launch_bounds__(256) void k5_mma(
    const float* __restrict__ W1l, const float* __restrict__ W1r,
    const float* __restrict__ b1,
    const float* __restrict__ W2l, const float* __restrict__ W2r)
{
    extern __shared__ __align__(16) char smem[];
    uint32_t sbu = smem_to_u32(smem);
    int tid = threadIdx.x, wid = tid >> 5, lane = tid & 31;
    int gidq = lane >> 2, tig = lane & 3;

    // ---- stage B split into ABUF0 regions (temporary) + W2T ----
    for (int idx = tid; idx < 128 * 128; idx += 256) {
        int n = idx >> 7, k = idx & 127;
        float w = (k < 64) ? W1l[n * 64 + k] : W1r[n * 64 + (k - 64)];
        __nv_bfloat16 h = __float2bfloat16(w);
        __nv_bfloat16 l = __float2bfloat16(w - __bfloat162float(h));
        *(__nv_bfloat16*)(smem + n * KPB + k * 2) = h;
        *(__nv_bfloat16*)(smem + 34816 + n * KPB + k * 2) = l;
    }
    for (int idx = tid; idx < 128 * 12; idx += 256) {
        int c = idx / 12, j = idx % 12;
        float w = (j < 6) ? W2l[j * 128 + c] : W2r[(j - 6) * 128 + c];
        *(float*)(smem + S_W2T + (size_t)(c * 12 + j) * 4) = w;
    }
    __syncthreads();

    // ---- hoist this warp's B fragments (n-slice = wid*16 .. +16) ----
    uint32_t bh0[8][2], bh1[8][2], bl0[8][2], bl1[8][2];
    {
        int lsel = lane & 15;
        int nr = (lsel & 7);
        int kb8 = ((lsel >> 3) & 1) * 16;
#pragma unroll
        for (int ks = 0; ks < 8; ks++)
#pragma unroll
            for (int nt = 0; nt < 2; nt++) {
                uint32_t addr = sbu + (uint32_t)((wid * 16 + nt * 8 + nr) * KPB + ks * 32 + kb8);
                ldm_x2(bh0[ks][nt], bh1[ks][nt], addr);
                ldm_x2(bl0[ks][nt], bl1[ks][nt], addr + 34816);
            }
    }
    float b1g[2][2];
#pragma unroll
    for (int nt = 0; nt < 2; nt++)
#pragma unroll
        for (int e = 0; e < 2; e++)
            b1g[nt][e] = b1[wid * 16 + nt * 8 + tig * 2 + e];
    __syncthreads();   // all frags read before cp.async overwrites ABUF0

    // ---- A staging (cp.async 16B chunks into padded rows) ----
    auto stageA = [&](int tileIdx, int buf) {
        int tb = min(tileIdx, TILES - 1) * 128;
        for (int c = tid; c < 2048; c += 256) {
            int row = c >> 4, wi = c & 15;
            int node = min(tb + row, TOT - 1);
            uint32_t dst = sbu + ABUF(buf) + row * KPB + wi * 16;
            cpa16(dst, g_ah + (size_t)node * 64 + wi * 4);
            cpa16(dst + 34816, g_al + (size_t)node * 64 + wi * 4);
        }
        CPA_COMMIT();
    };

    stageA(blockIdx.x, 0);
    int buf = 0;

    int arow_l = (lane & 7) + ((lane >> 3) & 1) * 8;
    int akb_l = (lane >> 4) * 16;

    for (int tile = blockIdx.x; tile < TILES; tile += gridDim.x) {
        stageA(tile + gridDim.x, buf ^ 1);
        CPA_WAIT1();
        __syncthreads();

        // ---- compute + immediate epilogue per mb (16 rows) ----
#pragma unroll 1
        for (int mb = 0; mb < 8; mb++) {
            // 6 independent accumulator chains: {hh, hl, lh} x {nt0, nt1}
            float ahh[2][4], ahl[2][4], alh[2][4];
#pragma unroll
            for (int nt = 0; nt < 2; nt++)
#pragma unroll
                for (int e = 0; e < 4; e++) { ahh[nt][e] = 0.f; ahl[nt][e] = 0.f; alh[nt][e] = 0.f; }

#pragma unroll
            for (int ks = 0; ks < 8; ks++) {
                uint32_t abase = sbu + ABUF(buf) + (uint32_t)((mb * 16 + arow_l) * KPB + ks * 32 + akb_l);
                uint32_t a0, a1, a2, a3, c0, c1, c2, c3;
                ldm_x4(a0, a1, a2, a3, abase);
                ldm_x4(c0, c1, c2, c3, abase + 34816);
#pragma unroll
                for (int nt = 0; nt < 2; nt++) {
                    mma16816(ahh[nt], a0, a1, a2, a3, bh0[ks][nt], bh1[ks][nt]);
                    mma16816(ahl[nt], a0, a1, a2, a3, bl0[ks][nt], bl1[ks][nt]);
                    mma16816(alh[nt], c0, c1, c2, c3, bh0[ks][nt], bh1[ks][nt]);
                }
            }

            // epilogue: combine terms, bias+relu, W2 projection, reduce over tig
            float p0[12], p1[12];
#pragma unroll
            for (int j = 0; j < 12; j++) { p0[j] = 0.f; p1[j] = 0.f; }
#pragma unroll
            for (int nt = 0; nt < 2; nt++)
#pragma unroll
                for (int e = 0; e < 2; e++) {
                    float bb = b1g[nt][e];
                    float v0 = (ahh[nt][e] + ahl[nt][e]) + alh[nt][e];
                    float v1 = (ahh[nt][2 + e] + ahl[nt][2 + e]) + alh[nt][2 + e];
                    float h0 = fmaxf(v0 + bb, 0.f);
                    float h1 = fmaxf(v1 + bb, 0.f);
                    int col = wid * 16 + nt * 8 + tig * 2 + e;
                    const float* wv = (const float*)(smem + S_W2T) + col * 12;
                    float4 w0 = *(const float4*)wv;
                    float4 w1 = *(const float4*)(wv + 4);
                    float4 w2 = *(const float4*)(wv + 8);
                    p0[0] += h0 * w0.x; p0[1] += h0 * w0.y; p0[2] += h0 * w0.z; p0[3] += h0 * w0.w;
                    p0[4] += h0 * w1.x; p0[5] += h0 * w1.y; p0[6] += h0 * w1.z; p0[7] += h0 * w1.w;
                    p0[8] += h0 * w2.x; p0[9] += h0 * w2.y; p0[10] += h0 * w2.z; p0[11] += h0 * w2.w;
                    p1[0] += h1 * w0.x; p1[1] += h1 * w0.y; p1[2] += h1 * w0.z; p1[3] += h1 * w0.w;
                    p1[4] += h1 * w1.x; p1[5] += h1 * w1.y; p1[6] += h1 * w1.z; p1[7] += h1 * w1.w;
                    p1[8] += h1 * w2.x; p1[9] += h1 * w2.y; p1[10] += h1 * w2.z; p1[11] += h1 * w2.w;
                }
#pragma unroll
            for (int o = 1; o <= 2; o <<= 1)
#pragma unroll
                for (int j = 0; j < 12; j++) {
                    p0[j] += __shfl_xor_sync(0xffffffffu, p0[j], o);
                    p1[j] += __shfl_xor_sync(0xffffffffu, p1[j], o);
                }
            if (tig == 0) {
                float* s0 = (float*)(smem + S_SAC2) + (size_t)(wid * 128 + mb * 16 + gidq) * 20;
                *(float4*)s0 = make_float4(p0[0], p0[1], p0[2], p0[3]);
                *(float4*)(s0 + 4) = make_float4(p0[4], p0[5], p0[6], p0[7]);
                *(float4*)(s0 + 8) = make_float4(p0[8], p0[9], p0[10], p0[11]);
                float* s1 = s0 + 8 * 20;
                *(float4*)s1 = make_float4(p1[0], p1[1], p1[2], p1[3]);
                *(float4*)(s1 + 4) = make_float4(p1[4], p1[5], p1[6], p1[7]);
                *(float4*)(s1 + 8) = make_float4(p1[8], p1[9], p1[10], p1[11]);
            }
        }
        __syncthreads();

        // ---- cross-warp reduce + writeout (threads 0..127 = rows) ----
        if (tid < 128) {
            int node = tile * 128 + tid;
            if (node < TOT) {
                float s[12];
#pragma unroll
                for (int j = 0; j < 12; j++) s[j] = 0.f;
#pragma unroll
                for (int w2 = 0; w2 < 8; w2++) {
                    const float* p = (const float*)(smem + S_SAC2) + (size_t)(w2 * 128 + tid) * 20;
                    float4 a = *(const float4*)p;
                    float4 b = *(const float4*)(p + 4);
                    float4 c = *(const float4*)(p + 8);
                    s[0] += a.x; s[1] += a.y; s[2] += a.z; s[3] += a.w;
                    s[4] += b.x; s[5] += b.y; s[6] += b.z; s[7] += b.w;
                    s[8] += c.x; s[9] += c.y; s[10] += c.z; s[11] += c.w;
                }
                float* gp = g_p + (size_t)node * 8;
                *(float4*)gp = make_float4(s[0], s[1], s[2], s[3]);
                *(float2*)(gp + 4) = make_float2(s[4], s[5]);
                float* gr = g_rr + (size_t)node * 8;
                *(float4*)gr = make_float4(s[6], s[7], s[8], s[9]);
                *(float2*)(gr + 4) = make_float2(s[10], s[11]);
            }
        }
        __syncthreads();
        buf ^= 1;
    }
}

// ---------------- K6: layer-2 aggregation + global max pool ----------------
#define K6_CHUNKS 157
__global__ void k6_layer2(const float* __restrict__ b2) {
    int t = blockIdx.x / K6_CHUNKS;
    int chunk = blockIdx.x % K6_CHUNKS;
    int i = chunk * 64 + (threadIdx.x >> 2);
    int q = threadIdx.x & 3;
    __shared__ unsigned zmax[6];
    if (threadIdx.x < 6) zmax[threadIdx.x] = 0u;
    __syncthreads();
    if (i < NN) {
        int node = t * NN + i;
        int deg = g_deg[node];
        int m = min(deg, CAP);
        const int* elist = g_slot + (size_t)node * CAP;
        int tb = t * NN;
        float s0 = 0, s1 = 0, s2 = 0, s3 = 0, s4 = 0, s5 = 0;
        for (int e = q; e < m; e += 4) {
            const float4* pp = (const float4*)(g_p + (size_t)(tb + elist[e]) * 8);
            float4 a = pp[0];
            float4 b = pp[1];
            s0 += a.x; s1 += a.y; s2 += a.z; s3 += a.w; s4 += b.x; s5 += b.y;
        }
#pragma unroll
        for (int o = 1; o <= 2; o <<= 1) {
            s0 += __shfl_xor_sync(0xffffffffu, s0, o);
            s1 += __shfl_xor_sync(0xffffffffu, s1, o);
            s2 += __shfl_xor_sync(0xffffffffu, s2, o);
            s3 += __shfl_xor_sync(0xffffffffu, s3, o);
            s4 += __shfl_xor_sync(0xffffffffu, s4, o);
            s5 += __shfl_xor_sync(0xffffffffu, s5, o);
        }
        if (q == 0) {
            float inv = 1.0f / (float)max(deg, 1);
            size_t base = (size_t)node * 8;
            atomicMax(&zmax[0], encf(s0 * inv + b2[0] + g_rr[base + 0]));
            atomicMax(&zmax[1], encf(s1 * inv + b2[1] + g_rr[base + 1]));
            atomicMax(&zmax[2], encf(s2 * inv + b2[2] + g_rr[base + 2]));
            atomicMax(&zmax[3], encf(s3 * inv + b2[3] + g_rr[base + 3]));
            atomicMax(&zmax[4], encf(s4 * inv + b2[4] + g_rr[base + 4]));
            atomicMax(&zmax[5], encf(s5 * inv + b2[5] + g_rr[base + 5]));
        }
    }
    __syncthreads();
    if (threadIdx.x < 6) atomicMax(&g_zenc[t * 8 + threadIdx.x], zmax[threadIdx.x]);
}

// ---------------- K7: GRU + NCE + outputs ----------------
__global__ void k7_final(const float* __restrict__ wih,
                         const float* __restrict__ bih,
                         const float* __restrict__ bhh,
                         float* __restrict__ out, int out_size)
{
    __shared__ float z[T * 6];
    __shared__ float gout[30 * 6];
    __shared__ float redf[256];
    __shared__ int   redi[256];
    int tid = threadIdx.x;
    for (int idx = tid; idx < T * 6; idx += 256)
        z[idx] = decf(g_zenc[(idx / 6) * 8 + (idx % 6)]);
    __syncthreads();
    if (tid < 180) {
        int t = tid / 6, j = tid % 6;
        float ar = 0.f, au = 0.f, an = 0.f;
#pragma unroll
        for (int d = 0; d < 6; d++) {
            float zv = z[t * 6 + d];
            ar += zv * wih[(0 + j) * 6 + d];
            au += zv * wih[(6 + j) * 6 + d];
            an += zv * wih[(12 + j) * 6 + d];
        }
        float r = 1.f / (1.f + expf(-(ar + bih[j]      + bhh[j])));
        float u = 1.f / (1.f + expf(-(au + bih[6 + j]  + bhh[6 + j])));
        float n = tanhf(an + bih[12 + j] + r * bhh[12 + j]);
        gout[tid] = (1.f - u) * n;
    }
    __syncthreads();
    float lnce = 0.f; int lc = 0;
    if (tid < 240) {
        int tp = tid / 12;
        int ii = tid % 12 + 1;
        int t = 10 + tp;
        const int joff[8] = {0, 11, 12, 13, 14, 15, 16, 17};
        float lg[8];
#pragma unroll
        for (int s = 0; s < 8; s++) {
            int idx = t + ii + joff[s];
            float d = 0.f;
#pragma unroll
            for (int c = 0; c < 6; c++) d += z[idx * 6 + c] * gout[t * 6 + c];
            lg[s] = d;
        }
        float m = lg[0];
#pragma unroll
        for (int s = 1; s < 8; s++) m = fmaxf(m, lg[s]);
        float se = 0.f;
#pragma unroll
        for (int s = 0; s < 8; s++) se += expf(lg[s] - m);
        lnce = lg[0] - m - logf(se);
        bool ok = true;
#pragma unroll
        for (int s = 1; s < 8; s++) if (lg[s] > lg[0]) ok = false;
        lc = ok ? 1 : 0;
    }
    redf[tid] = lnce; redi[tid] = lc;
    __syncthreads();
    for (int o = 128; o > 0; o >>= 1) {
        if (tid < o) { redf[tid] += redf[tid + o]; redi[tid] += redi[tid + o]; }
        __syncthreads();
    }
    if (tid == 0) {
        if (out_size > 0) out[0] = redf[0] / (-240.0f);
        if (out_size > 1) out[1] = (float)redi[0] / 240.0f;
    }
    if (tid < 180 && (2 + tid) < out_size) out[2 + tid] = gout[tid];
    for (int idx = 182 + tid; idx < out_size; idx += 256) out[idx] = 0.f;
}

// ---------------- launch ----------------
extern "C" void kernel_launch(void* const* d_in, const int* in_sizes, int n_in,
                              void* d_out, int out_size)
{
    const float* x   = (const float*)d_in[0];
    const int*   ei  = (const int*)  d_in[1];
    const float* W1l = (const float*)d_in[2];
    const float* W1r = (const float*)d_in[3];
    const float* b1  = (const float*)d_in[4];
    const float* W2l = (const float*)d_in[5];
    const float* W2r = (const float*)d_in[6];
    const float* b2  = (const float*)d_in[7];
    const float* wih = (const float*)d_in[8];
    const float* bih = (const float*)d_in[10];
    const float* bhh = (const float*)d_in[11];
    float* out = (float*)d_out;

    cudaFuncSetAttribute(k5_mma, cudaFuncAttributeMaxDynamicSharedMemorySize, S_TOTAL);

    k0_init <<<(TOT + 255) / 256, 256>>>();
    k1_build<<<(T * (EE / 8) + 255) / 256, 256>>>(ei);
    k4a_agg <<<(TOT * 32 + 255) / 256, 256>>>(x);
    k5_mma  <<<148, 256, S_TOTAL>>>(W1l, W1r, b1, W2l, W2r);
    k6_layer2<<<T * K6_CHUNKS, 256>>>(b2);
    k7_final<<<1, 256>>>(wih, bih, bhh, out, out_size);
}

// round 10
// speedup vs baseline: 1.1220x; 1.1216x over previous
#include <cuda_runtime.h>
#include <cuda_bf16.h>
#include <cstdint>
#include <cstddef>
#include <math.h>

#define T    60
#define NN   10000
#define EE   160000
#define INC  64
#define CAP  64
#define TOT  (T * NN)
#define TILES ((TOT + 127) / 128)

// ---------------- scratch ----------------
__device__ int      g_deg [TOT];
__device__ int      g_slot[(size_t)TOT * CAP];
__device__ uint32_t g_ah[(size_t)TOT * 64];   // bf16x2 rows: [mean(0..63)|x(64..127)] hi
__device__ uint32_t g_al[(size_t)TOT * 64];   // residual lo
__device__ float    g_p   [(size_t)TOT * 8];
__device__ float    g_rr  [(size_t)TOT * 8];
__device__ unsigned g_zenc[T * 8];

__device__ __forceinline__ unsigned encf(float f) {
    unsigned u = __float_as_uint(f);
    return (u & 0x80000000u) ? ~u : (u | 0x80000000u);
}
__device__ __forceinline__ float decf(unsigned u) {
    return (u & 0x80000000u) ? __uint_as_float(u & 0x7fffffffu) : __uint_as_float(~u);
}

// ---------------- K0: init ----------------
__global__ void k0_init() {
    int idx = blockIdx.x * blockDim.x + threadIdx.x;
    if (idx < TOT) g_deg[idx] = 0;
    if (idx < T * 8) g_zenc[idx] = 0u;
}

// ---------------- K1: single-pass bucketed CSR build (8 edges/thread) ----------------
__global__ void k1_build(const int* __restrict__ ei) {
    int q = blockIdx.x * blockDim.x + threadIdx.x;
    if (q >= T * (EE / 8)) return;
    int t = q / (EE / 8);
    int e = (q - t * (EE / 8)) * 8;
    const int* sp = ei + (size_t)t * 2 * EE + e;
    int4 sva = *(const int4*)sp;
    int4 svb = *(const int4*)(sp + 4);
    int4 dva = *(const int4*)(sp + EE);
    int4 dvb = *(const int4*)(sp + EE + 4);
    int tb = t * NN;
    int d0 = tb + dva.x, d1 = tb + dva.y, d2 = tb + dva.z, d3 = tb + dva.w;
    int d4 = tb + dvb.x, d5 = tb + dvb.y, d6 = tb + dvb.z, d7 = tb + dvb.w;
    int p0 = atomicAdd(&g_deg[d0], 1);
    int p1 = atomicAdd(&g_deg[d1], 1);
    int p2 = atomicAdd(&g_deg[d2], 1);
    int p3 = atomicAdd(&g_deg[d3], 1);
    int p4 = atomicAdd(&g_deg[d4], 1);
    int p5 = atomicAdd(&g_deg[d5], 1);
    int p6 = atomicAdd(&g_deg[d6], 1);
    int p7 = atomicAdd(&g_deg[d7], 1);
    if (p0 < CAP) g_slot[(size_t)d0 * CAP + p0] = sva.x;
    if (p1 < CAP) g_slot[(size_t)d1 * CAP + p1] = sva.y;
    if (p2 < CAP) g_slot[(size_t)d2 * CAP + p2] = sva.z;
    if (p3 < CAP) g_slot[(size_t)d3 * CAP + p3] = sva.w;
    if (p4 < CAP) g_slot[(size_t)d4 * CAP + p4] = svb.x;
    if (p5 < CAP) g_slot[(size_t)d5 * CAP + p5] = svb.y;
    if (p6 < CAP) g_slot[(size_t)d6 * CAP + p6] = svb.z;
    if (p7 < CAP) g_slot[(size_t)d7 * CAP + p7] = svb.w;
}

// ---------------- bf16 split helpers ----------------
__device__ __forceinline__ void split2(float a, float b, uint32_t& hi, uint32_t& lo) {
    __nv_bfloat162 h = __floats2bfloat162_rn(a, b);
    float ra = a - __bfloat162float(h.x);
    float rb = b - __bfloat162float(h.y);
    __nv_bfloat162 l = __floats2bfloat162_rn(ra, rb);
    hi = *(uint32_t*)&h;
    lo = *(uint32_t*)&l;
}

// ---------------- K4a: mean aggregation + split-bf16 A-row emit (warp/node) ----------------
__global__ void k4a_agg(const float* __restrict__ x) {
    int w = (blockIdx.x * blockDim.x + threadIdx.x) >> 5;
    int lane = threadIdx.x & 31;
    if (w >= TOT) return;
    int node = w;
    int t = node / NN;
    int deg = g_deg[node];
    int m = min(deg, CAP);
    const int* elist = g_slot + (size_t)node * CAP;
    const float* xt = x + (size_t)t * NN * INC;
    float sx = 0.f, sy = 0.f;
    int e = 0;
    for (; e + 8 <= m; e += 8) {
        int s0 = elist[e+0], s1 = elist[e+1], s2 = elist[e+2], s3 = elist[e+3];
        int s4 = elist[e+4], s5 = elist[e+5], s6 = elist[e+6], s7 = elist[e+7];
        float2 v0 = ((const float2*)(xt + (size_t)s0 * INC))[lane];
        float2 v1 = ((const float2*)(xt + (size_t)s1 * INC))[lane];
        float2 v2 = ((const float2*)(xt + (size_t)s2 * INC))[lane];
        float2 v3 = ((const float2*)(xt + (size_t)s3 * INC))[lane];
        float2 v4 = ((const float2*)(xt + (size_t)s4 * INC))[lane];
        float2 v5 = ((const float2*)(xt + (size_t)s5 * INC))[lane];
        float2 v6 = ((const float2*)(xt + (size_t)s6 * INC))[lane];
        float2 v7 = ((const float2*)(xt + (size_t)s7 * INC))[lane];
        sx += ((v0.x + v1.x) + (v2.x + v3.x)) + ((v4.x + v5.x) + (v6.x + v7.x));
        sy += ((v0.y + v1.y) + (v2.y + v3.y)) + ((v4.y + v5.y) + (v6.y + v7.y));
    }
    for (; e < m; e++) {
        int s0 = elist[e];
        float2 v0 = ((const float2*)(xt + (size_t)s0 * INC))[lane];
        sx += v0.x; sy += v0.y;
    }
    float inv = 1.0f / (float)max(deg, 1);
    uint32_t hi, lo;
    split2(sx * inv, sy * inv, hi, lo);
    g_ah[(size_t)node * 64 + lane] = hi;
    g_al[(size_t)node * 64 + lane] = lo;
    float2 xv = ((const float2*)(x + (size_t)node * INC))[lane];
    split2(xv.x, xv.y, hi, lo);
    g_ah[(size_t)node * 64 + 32 + lane] = hi;
    g_al[(size_t)node * 64 + 32 + lane] = lo;
}

// ---------------- mma / ldmatrix / cp.async helpers ----------------
__device__ __forceinline__ void mma16816(float* c,
    uint32_t a0, uint32_t a1, uint32_t a2, uint32_t a3, uint32_t b0, uint32_t b1)
{
    asm volatile(
        "mma.sync.aligned.m16n8k16.row.col.f32.bf16.bf16.f32 "
        "{%0,%1,%2,%3}, {%4,%5,%6,%7}, {%8,%9}, {%0,%1,%2,%3};"
        : "+f"(c[0]), "+f"(c[1]), "+f"(c[2]), "+f"(c[3])
        : "r"(a0), "r"(a1), "r"(a2), "r"(a3), "r"(b0), "r"(b1));
}
__device__ __forceinline__ void ldm_x4(uint32_t& r0, uint32_t& r1, uint32_t& r2, uint32_t& r3, uint32_t a) {
    asm volatile("ldmatrix.sync.aligned.m8n8.x4.shared.b16 {%0,%1,%2,%3}, [%4];"
        : "=r"(r0), "=r"(r1), "=r"(r2), "=r"(r3) : "r"(a));
}
__device__ __forceinline__ void ldm_x2(uint32_t& r0, uint32_t& r1, uint32_t a) {
    asm volatile("ldmatrix.sync.aligned.m8n8.x2.shared.b16 {%0,%1}, [%2];"
        : "=r"(r0), "=r"(r1) : "r"(a));
}
__device__ __forceinline__ void cpa16(uint32_t dst, const void* src) {
    asm volatile("cp.async.cg.shared.global [%0], [%1], 16;" :: "r"(dst), "l"(src) : "memory");
}
#define CPA_COMMIT() asm volatile("cp.async.commit_group;" ::: "memory")
#define CPA_WAIT1()  asm volatile("cp.async.wait_group 1;" ::: "memory")
__device__ __forceinline__ uint32_t smem_to_u32(const void* p) {
    uint32_t a;
    asm("{ .reg .u64 t; cvta.to.shared.u64 t, %1; cvt.u32.u64 %0, t; }" : "=r"(a) : "l"(p));
    return a;
}
__device__ __forceinline__ uint32_t pack_bf16x2(float lo, float hi) {
    __nv_bfloat162 h = __floats2bfloat162_rn(lo, hi);
    return *(uint32_t*)&h;
}

// smem layout (bytes); padded A rows: 272 B (conflict-free ldmatrix)
#define KPB    272
#define ABUF(b) ((b) * 69632)          // each buf: hi @ +0 (34816), lo @ +34816
#define S_SAC2 139264                  // [8 warps][128 rows][20 floats] = 81920
#define S_TOTAL 221184

// ---------------- K5: HMMA split GEMM, W2 projection also on tensor pipe ----------------
__global__ __launch_bounds__(256) void k5_mma(
    const float* __restrict__ W1l, const float* __restrict__ W1r,
    const float* __restrict__ b1,
    const float* __restrict__ W2l, const float* __restrict__ W2r)
{
    extern __shared__ __align__(16) char smem[];
    uint32_t sbu = smem_to_u32(smem);
    int tid = threadIdx.x, wid = tid >> 5, lane = tid & 31;
    int gidq = lane >> 2, tig = lane & 3;

    // ---- stage B1-layer weights split into ABUF0 (temporary) ----
    for (int idx = tid; idx < 128 * 128; idx += 256) {
        int n = idx >> 7, k = idx & 127;
        float w = (k < 64) ? W1l[n * 64 + k] : W1r[n * 64 + (k - 64)];
        __nv_bfloat16 h = __float2bfloat16(w);
        __nv_bfloat16 l = __float2bfloat16(w - __bfloat162float(h));
        *(__nv_bfloat16*)(smem + n * KPB + k * 2) = h;
        *(__nv_bfloat16*)(smem + 34816 + n * KPB + k * 2) = l;
    }
    __syncthreads();

    // ---- hoist this warp's W1 B fragments (n-slice = wid*16 .. +16) ----
    uint32_t bh0[8][2], bh1[8][2], bl0[8][2], bl1[8][2];
    {
        int lsel = lane & 15;
        int nr = (lsel & 7);
        int kb8 = ((lsel >> 3) & 1) * 16;
#pragma unroll
        for (int ks = 0; ks < 8; ks++)
#pragma unroll
            for (int nt = 0; nt < 2; nt++) {
                uint32_t addr = sbu + (uint32_t)((wid * 16 + nt * 8 + nr) * KPB + ks * 32 + kb8);
                ldm_x2(bh0[ks][nt], bh1[ks][nt], addr);
                ldm_x2(bl0[ks][nt], bl1[ks][nt], addr + 34816);
            }
    }
    float b1g[2][2];
#pragma unroll
    for (int nt = 0; nt < 2; nt++)
#pragma unroll
        for (int e = 0; e < 2; e++)
            b1g[nt][e] = b1[wid * 16 + nt * 8 + tig * 2 + e];

    // ---- W2 projection B-fragments (register resident, split hi/res) ----
    // projection: P[16rows x 16n] = H[16 x 16k(local)] @ W2T[16k x 16n]
    // B frag (col-major KxN): b0 = (k=2tig..+1, n=gidq), b1 = (k=2tig+8..+9, n=gidq)
    uint32_t w2h_b0[2], w2h_b1[2], w2r_b0[2], w2r_b1[2];
    {
#pragma unroll
        for (int np = 0; np < 2; np++) {
            int n = np * 8 + gidq;   // output channel (0..15; >=12 padded 0)
            float wv[4];
#pragma unroll
            for (int kk = 0; kk < 4; kk++) {
                int c = wid * 16 + tig * 2 + (kk & 1) + (kk >> 1) * 8;
                float w = 0.f;
                if (n < 6)       w = W2l[n * 128 + c];
                else if (n < 12) w = W2r[(n - 6) * 128 + c];
                wv[kk] = w;
            }
            // hi parts
            __nv_bfloat162 h0 = __floats2bfloat162_rn(wv[0], wv[1]);
            __nv_bfloat162 h1 = __floats2bfloat162_rn(wv[2], wv[3]);
            w2h_b0[np] = *(uint32_t*)&h0;
            w2h_b1[np] = *(uint32_t*)&h1;
            // residuals
            w2r_b0[np] = pack_bf16x2(wv[0] - __bfloat162float(h0.x), wv[1] - __bfloat162float(h0.y));
            w2r_b1[np] = pack_bf16x2(wv[2] - __bfloat162float(h1.x), wv[3] - __bfloat162float(h1.y));
        }
    }
    __syncthreads();   // all frags read before cp.async overwrites ABUF0

    // ---- A staging (cp.async 16B chunks into padded rows) ----
    auto stageA = [&](int tileIdx, int buf) {
        int tb = min(tileIdx, TILES - 1) * 128;
        for (int c = tid; c < 2048; c += 256) {
            int row = c >> 4, wi = c & 15;
            int node = min(tb + row, TOT - 1);
            uint32_t dst = sbu + ABUF(buf) + row * KPB + wi * 16;
            cpa16(dst, g_ah + (size_t)node * 64 + wi * 4);
            cpa16(dst + 34816, g_al + (size_t)node * 64 + wi * 4);
        }
        CPA_COMMIT();
    };

    stageA(blockIdx.x, 0);
    int buf = 0;

    int arow_l = (lane & 7) + ((lane >> 3) & 1) * 8;
    int akb_l = (lane >> 4) * 16;

    for (int tile = blockIdx.x; tile < TILES; tile += gridDim.x) {
        stageA(tile + gridDim.x, buf ^ 1);
        CPA_WAIT1();
        __syncthreads();

        // ---- compute + tensor-pipe epilogue per mb (16 rows) ----
#pragma unroll 1
        for (int mb = 0; mb < 8; mb++) {
            float ahh[2][4], ahl[2][4], alh[2][4];
#pragma unroll
            for (int nt = 0; nt < 2; nt++)
#pragma unroll
                for (int e = 0; e < 4; e++) { ahh[nt][e] = 0.f; ahl[nt][e] = 0.f; alh[nt][e] = 0.f; }

#pragma unroll
            for (int ks = 0; ks < 8; ks++) {
                uint32_t abase = sbu + ABUF(buf) + (uint32_t)((mb * 16 + arow_l) * KPB + ks * 32 + akb_l);
                uint32_t a0, a1, a2, a3, c0, c1, c2, c3;
                ldm_x4(a0, a1, a2, a3, abase);
                ldm_x4(c0, c1, c2, c3, abase + 34816);
#pragma unroll
                for (int nt = 0; nt < 2; nt++) {
                    mma16816(ahh[nt], a0, a1, a2, a3, bh0[ks][nt], bh1[ks][nt]);
                    mma16816(ahl[nt], a0, a1, a2, a3, bl0[ks][nt], bl1[ks][nt]);
                    mma16816(alh[nt], c0, c1, c2, c3, bh0[ks][nt], bh1[ks][nt]);
                }
            }

            // h = relu(sum + bias), split to bf16 hi/lo as A-fragments of projection MMA
            float h[2][4];
#pragma unroll
            for (int nt = 0; nt < 2; nt++)
#pragma unroll
                for (int e = 0; e < 4; e++) {
                    float v = (ahh[nt][e] + ahl[nt][e]) + alh[nt][e] + b1g[nt][e & 1];
                    h[nt][e] = fmaxf(v, 0.f);
                }
            // A frag: a0=(row gidq, k=2tig..), a1=(row gidq+8, k=2tig..), a2/a3 = k+8 (nt=1 block)
            uint32_t pa0h, pa0l, pa1h, pa1l, pa2h, pa2l, pa3h, pa3l;
            split2(h[0][0], h[0][1], pa0h, pa0l);
            split2(h[0][2], h[0][3], pa1h, pa1l);
            split2(h[1][0], h[1][1], pa2h, pa2l);
            split2(h[1][2], h[1][3], pa3h, pa3l);

            float accP[2][4];
#pragma unroll
            for (int np = 0; np < 2; np++) {
#pragma unroll
                for (int e = 0; e < 4; e++) accP[np][e] = 0.f;
                mma16816(accP[np], pa0h, pa1h, pa2h, pa3h, w2h_b0[np], w2h_b1[np]);
                mma16816(accP[np], pa0l, pa1l, pa2l, pa3l, w2h_b0[np], w2h_b1[np]);
                mma16816(accP[np], pa0h, pa1h, pa2h, pa3h, w2r_b0[np], w2r_b1[np]);
            }

            // store P fragments to slab: C layout rows gidq/gidq+8, cols np*8 + 2tig..+1
            float* s0 = (float*)(smem + S_SAC2) + (size_t)(wid * 128 + mb * 16 + gidq) * 20;
#pragma unroll
            for (int np = 0; np < 2; np++) {
                *(float2*)(s0 + np * 8 + 2 * tig)            = make_float2(accP[np][0], accP[np][1]);
                *(float2*)(s0 + 8 * 20 + np * 8 + 2 * tig)   = make_float2(accP[np][2], accP[np][3]);
            }
        }
        __syncthreads();

        // ---- cross-warp reduce + writeout (threads 0..127 = rows) ----
        if (tid < 128) {
            int node = tile * 128 + tid;
            if (node < TOT) {
                float s[12];
#pragma unroll
                for (int j = 0; j < 12; j++) s[j] = 0.f;
#pragma unroll
                for (int w2 = 0; w2 < 8; w2++) {
                    const float* p = (const float*)(smem + S_SAC2) + (size_t)(w2 * 128 + tid) * 20;
                    float4 a = *(const float4*)p;
                    float4 b = *(const float4*)(p + 4);
                    float4 c = *(const float4*)(p + 8);
                    s[0] += a.x; s[1] += a.y; s[2] += a.z; s[3] += a.w;
                    s[4] += b.x; s[5] += b.y; s[6] += b.z; s[7] += b.w;
                    s[8] += c.x; s[9] += c.y; s[10] += c.z; s[11] += c.w;
                }
                float* gp = g_p + (size_t)node * 8;
                *(float4*)gp = make_float4(s[0], s[1], s[2], s[3]);
                *(float2*)(gp + 4) = make_float2(s[4], s[5]);
                float* gr = g_rr + (size_t)node * 8;
                *(float4*)gr = make_float4(s[6], s[7], s[8], s[9]);
                *(float2*)(gr + 4) = make_float2(s[10], s[11]);
            }
        }
        __syncthreads();
        buf ^= 1;
    }
}

// ---------------- K6: layer-2 aggregation + global max pool ----------------
#define K6_CHUNKS 157
__global__ void k6_layer2(const float* __restrict__ b2) {
    int t = blockIdx.x / K6_CHUNKS;
    int chunk = blockIdx.x % K6_CHUNKS;
    int i = chunk * 64 + (threadIdx.x >> 2);
    int q = threadIdx.x & 3;
    __shared__ unsigned zmax[6];
    if (threadIdx.x < 6) zmax[threadIdx.x] = 0u;
    __syncthreads();
    if (i < NN) {
        int node = t * NN + i;
        int deg = g_deg[node];
        int m = min(deg, CAP);
        const int* elist = g_slot + (size_t)node * CAP;
        int tb = t * NN;
        float s0 = 0, s1 = 0, s2 = 0, s3 = 0, s4 = 0, s5 = 0;
        for (int e = q; e < m; e += 4) {
            const float4* pp = (const float4*)(g_p + (size_t)(tb + elist[e]) * 8);
            float4 a = pp[0];
            float4 b = pp[1];
            s0 += a.x; s1 += a.y; s2 += a.z; s3 += a.w; s4 += b.x; s5 += b.y;
        }
#pragma unroll
        for (int o = 1; o <= 2; o <<= 1) {
            s0 += __shfl_xor_sync(0xffffffffu, s0, o);
            s1 += __shfl_xor_sync(0xffffffffu, s1, o);
            s2 += __shfl_xor_sync(0xffffffffu, s2, o);
            s3 += __shfl_xor_sync(0xffffffffu, s3, o);
            s4 += __shfl_xor_sync(0xffffffffu, s4, o);
            s5 += __shfl_xor_sync(0xffffffffu, s5, o);
        }
        if (q == 0) {
            float inv = 1.0f / (float)max(deg, 1);
            size_t base = (size_t)node * 8;
            atomicMax(&zmax[0], encf(s0 * inv + b2[0] + g_rr[base + 0]));
            atomicMax(&zmax[1], encf(s1 * inv + b2[1] + g_rr[base + 1]));
            atomicMax(&zmax[2], encf(s2 * inv + b2[2] + g_rr[base + 2]));
            atomicMax(&zmax[3], encf(s3 * inv + b2[3] + g_rr[base + 3]));
            atomicMax(&zmax[4], encf(s4 * inv + b2[4] + g_rr[base + 4]));
            atomicMax(&zmax[5], encf(s5 * inv + b2[5] + g_rr[base + 5]));
        }
    }
    __syncthreads();
    if (threadIdx.x < 6) atomicMax(&g_zenc[t * 8 + threadIdx.x], zmax[threadIdx.x]);
}

// ---------------- K7: GRU + NCE + outputs ----------------
__global__ void k7_final(const float* __restrict__ wih,
                         const float* __restrict__ bih,
                         const float* __restrict__ bhh,
                         float* __restrict__ out, int out_size)
{
    __shared__ float z[T * 6];
    __shared__ float gout[30 * 6];
    __shared__ float redf[256];
    __shared__ int   redi[256];
    int tid = threadIdx.x;
    for (int idx = tid; idx < T * 6; idx += 256)
        z[idx] = decf(g_zenc[(idx / 6) * 8 + (idx % 6)]);
    __syncthreads();
    if (tid < 180) {
        int t = tid / 6, j = tid % 6;
        float ar = 0.f, au = 0.f, an = 0.f;
#pragma unroll
        for (int d = 0; d < 6; d++) {
            float zv = z[t * 6 + d];
            ar += zv * wih[(0 + j) * 6 + d];
            au += zv * wih[(6 + j) * 6 + d];
            an += zv * wih[(12 + j) * 6 + d];
        }
        float r = 1.f / (1.f + expf(-(ar + bih[j]      + bhh[j])));
        float u = 1.f / (1.f + expf(-(au + bih[6 + j]  + bhh[6 + j])));
        float n = tanhf(an + bih[12 + j] + r * bhh[12 + j]);
        gout[tid] = (1.f - u) * n;
    }
    __syncthreads();
    float lnce = 0.f; int lc = 0;
    if (tid < 240) {
        int tp = tid / 12;
        int ii = tid % 12 + 1;
        int t = 10 + tp;
        const int joff[8] = {0, 11, 12, 13, 14, 15, 16, 17};
        float lg[8];
#pragma unroll
        for (int s = 0; s < 8; s++) {
            int idx = t + ii + joff[s];
            float d = 0.f;
#pragma unroll
            for (int c = 0; c < 6; c++) d += z[idx * 6 + c] * gout[t * 6 + c];
            lg[s] = d;
        }
        float m = lg[0];
#pragma unroll
        for (int s = 1; s < 8; s++) m = fmaxf(m, lg[s]);
        float se = 0.f;
#pragma unroll
        for (int s = 0; s < 8; s++) se += expf(lg[s] - m);
        lnce = lg[0] - m - logf(se);
        bool ok = true;
#pragma unroll
        for (int s = 1; s < 8; s++) if (lg[s] > lg[0]) ok = false;
        lc = ok ? 1 : 0;
    }
    redf[tid] = lnce; redi[tid] = lc;
    __syncthreads();
    for (int o = 128; o > 0; o >>= 1) {
        if (tid < o) { redf[tid] += redf[tid + o]; redi[tid] += redi[tid + o]; }
        __syncthreads();
    }
    if (tid == 0) {
        if (out_size > 0) out[0] = redf[0] / (-240.0f);
        if (out_size > 1) out[1] = (float)redi[0] / 240.0f;
    }
    if (tid < 180 && (2 + tid) < out_size) out[2 + tid] = gout[tid];
    for (int idx = 182 + tid; idx < out_size; idx += 256) out[idx] = 0.f;
}

// ---------------- launch ----------------
extern "C" void kernel_launch(void* const* d_in, const int* in_sizes, int n_in,
                              void* d_out, int out_size)
{
    const float* x   = (const float*)d_in[0];
    const int*   ei  = (const int*)  d_in[1];
    const float* W1l = (const float*)d_in[2];
    const float* W1r = (const float*)d_in[3];
    const float* b1  = (const float*)d_in[4];
    const float* W2l = (const float*)d_in[5];
    const float* W2r = (const float*)d_in[6];
    const float* b2  = (const float*)d_in[7];
    const float* wih = (const float*)d_in[8];
    const float* bih = (const float*)d_in[10];
    const float* bhh = (const float*)d_in[11];
    float* out = (float*)d_out;

    cudaFuncSetAttribute(k5_mma, cudaFuncAttributeMaxDynamicSharedMemorySize, S_TOTAL);

    k0_init <<<(TOT + 255) / 256, 256>>>();
    k1_build<<<(T * (EE / 8) + 255) / 256, 256>>>(ei);
    k4a_agg <<<(TOT * 32 + 255) / 256, 256>>>(x);
    k5_mma  <<<148, 256, S_TOTAL>>>(W1l, W1r, b1, W2l, W2r);
    k6_layer2<<<T * K6_CHUNKS, 256>>>(b2);
    k7_final<<<1, 256>>>(wih, bih, bhh, out, out_size);
}

// round 11
// speedup vs baseline: 1.1284x; 1.0057x over previous
#include <cuda_runtime.h>
#include <cuda_bf16.h>
#include <cstdint>
#include <cstddef>
#include <math.h>

#define T    60
#define NN   10000
#define EE   160000
#define INC  64
#define CAP  64
#define TOT  (T * NN)
#define TILES ((TOT + 127) / 128)

// ---------------- scratch ----------------
__device__ int      g_deg [TOT];
__device__ int      g_slot[(size_t)TOT * CAP];
__device__ uint32_t g_ah[(size_t)TOT * 64];   // bf16x2 rows: [mean(0..63)|x(64..127)] hi
__device__ uint32_t g_al[(size_t)TOT * 64];   // residual lo
__device__ float    g_p   [(size_t)TOT * 8];
__device__ float    g_rr  [(size_t)TOT * 8];
__device__ unsigned g_zenc[T * 8];

__device__ __forceinline__ unsigned encf(float f) {
    unsigned u = __float_as_uint(f);
    return (u & 0x80000000u) ? ~u : (u | 0x80000000u);
}
__device__ __forceinline__ float decf(unsigned u) {
    return (u & 0x80000000u) ? __uint_as_float(u & 0x7fffffffu) : __uint_as_float(~u);
}

// ---------------- K0: init ----------------
__global__ void k0_init() {
    int idx = blockIdx.x * blockDim.x + threadIdx.x;
    if (idx < TOT) g_deg[idx] = 0;
    if (idx < T * 8) g_zenc[idx] = 0u;
}

// ---------------- K1: single-pass bucketed CSR build (8 edges/thread) ----------------
__global__ void k1_build(const int* __restrict__ ei) {
    int q = blockIdx.x * blockDim.x + threadIdx.x;
    if (q >= T * (EE / 8)) return;
    int t = q / (EE / 8);
    int e = (q - t * (EE / 8)) * 8;
    const int* sp = ei + (size_t)t * 2 * EE + e;
    int4 sva = *(const int4*)sp;
    int4 svb = *(const int4*)(sp + 4);
    int4 dva = *(const int4*)(sp + EE);
    int4 dvb = *(const int4*)(sp + EE + 4);
    int tb = t * NN;
    int d0 = tb + dva.x, d1 = tb + dva.y, d2 = tb + dva.z, d3 = tb + dva.w;
    int d4 = tb + dvb.x, d5 = tb + dvb.y, d6 = tb + dvb.z, d7 = tb + dvb.w;
    int p0 = atomicAdd(&g_deg[d0], 1);
    int p1 = atomicAdd(&g_deg[d1], 1);
    int p2 = atomicAdd(&g_deg[d2], 1);
    int p3 = atomicAdd(&g_deg[d3], 1);
    int p4 = atomicAdd(&g_deg[d4], 1);
    int p5 = atomicAdd(&g_deg[d5], 1);
    int p6 = atomicAdd(&g_deg[d6], 1);
    int p7 = atomicAdd(&g_deg[d7], 1);
    if (p0 < CAP) g_slot[(size_t)d0 * CAP + p0] = sva.x;
    if (p1 < CAP) g_slot[(size_t)d1 * CAP + p1] = sva.y;
    if (p2 < CAP) g_slot[(size_t)d2 * CAP + p2] = sva.z;
    if (p3 < CAP) g_slot[(size_t)d3 * CAP + p3] = sva.w;
    if (p4 < CAP) g_slot[(size_t)d4 * CAP + p4] = svb.x;
    if (p5 < CAP) g_slot[(size_t)d5 * CAP + p5] = svb.y;
    if (p6 < CAP) g_slot[(size_t)d6 * CAP + p6] = svb.z;
    if (p7 < CAP) g_slot[(size_t)d7 * CAP + p7] = svb.w;
}

// ---------------- bf16 split helpers ----------------
__device__ __forceinline__ void split2(float a, float b, uint32_t& hi, uint32_t& lo) {
    __nv_bfloat162 h = __floats2bfloat162_rn(a, b);
    float ra = a - __bfloat162float(h.x);
    float rb = b - __bfloat162float(h.y);
    __nv_bfloat162 l = __floats2bfloat162_rn(ra, rb);
    hi = *(uint32_t*)&h;
    lo = *(uint32_t*)&l;
}

// ---------------- K4a: mean aggregation + split-bf16 A-row emit (warp/node) ----------------
__global__ void k4a_agg(const float* __restrict__ x) {
    int w = (blockIdx.x * blockDim.x + threadIdx.x) >> 5;
    int lane = threadIdx.x & 31;
    if (w >= TOT) return;
    int node = w;
    int t = node / NN;
    int deg = g_deg[node];
    int m = min(deg, CAP);
    const int* elist = g_slot + (size_t)node * CAP;
    const float* xt = x + (size_t)t * NN * INC;
    float sx = 0.f, sy = 0.f;
    int e = 0;
    for (; e + 8 <= m; e += 8) {
        int s0 = elist[e+0], s1 = elist[e+1], s2 = elist[e+2], s3 = elist[e+3];
        int s4 = elist[e+4], s5 = elist[e+5], s6 = elist[e+6], s7 = elist[e+7];
        float2 v0 = ((const float2*)(xt + (size_t)s0 * INC))[lane];
        float2 v1 = ((const float2*)(xt + (size_t)s1 * INC))[lane];
        float2 v2 = ((const float2*)(xt + (size_t)s2 * INC))[lane];
        float2 v3 = ((const float2*)(xt + (size_t)s3 * INC))[lane];
        float2 v4 = ((const float2*)(xt + (size_t)s4 * INC))[lane];
        float2 v5 = ((const float2*)(xt + (size_t)s5 * INC))[lane];
        float2 v6 = ((const float2*)(xt + (size_t)s6 * INC))[lane];
        float2 v7 = ((const float2*)(xt + (size_t)s7 * INC))[lane];
        sx += ((v0.x + v1.x) + (v2.x + v3.x)) + ((v4.x + v5.x) + (v6.x + v7.x));
        sy += ((v0.y + v1.y) + (v2.y + v3.y)) + ((v4.y + v5.y) + (v6.y + v7.y));
    }
    for (; e < m; e++) {
        int s0 = elist[e];
        float2 v0 = ((const float2*)(xt + (size_t)s0 * INC))[lane];
        sx += v0.x; sy += v0.y;
    }
    float inv = 1.0f / (float)max(deg, 1);
    uint32_t hi, lo;
    split2(sx * inv, sy * inv, hi, lo);
    g_ah[(size_t)node * 64 + lane] = hi;
    g_al[(size_t)node * 64 + lane] = lo;
    float2 xv = ((const float2*)(x + (size_t)node * INC))[lane];
    split2(xv.x, xv.y, hi, lo);
    g_ah[(size_t)node * 64 + 32 + lane] = hi;
    g_al[(size_t)node * 64 + 32 + lane] = lo;
}

// ---------------- mma / ldmatrix / cp.async helpers ----------------
__device__ __forceinline__ void mma16816(float* c,
    uint32_t a0, uint32_t a1, uint32_t a2, uint32_t a3, uint32_t b0, uint32_t b1)
{
    asm volatile(
        "mma.sync.aligned.m16n8k16.row.col.f32.bf16.bf16.f32 "
        "{%0,%1,%2,%3}, {%4,%5,%6,%7}, {%8,%9}, {%0,%1,%2,%3};"
        : "+f"(c[0]), "+f"(c[1]), "+f"(c[2]), "+f"(c[3])
        : "r"(a0), "r"(a1), "r"(a2), "r"(a3), "r"(b0), "r"(b1));
}
__device__ __forceinline__ void ldm_x4(uint32_t& r0, uint32_t& r1, uint32_t& r2, uint32_t& r3, uint32_t a) {
    asm volatile("ldmatrix.sync.aligned.m8n8.x4.shared.b16 {%0,%1,%2,%3}, [%4];"
        : "=r"(r0), "=r"(r1), "=r"(r2), "=r"(r3) : "r"(a));
}
__device__ __forceinline__ void ldm_x2(uint32_t& r0, uint32_t& r1, uint32_t a) {
    asm volatile("ldmatrix.sync.aligned.m8n8.x2.shared.b16 {%0,%1}, [%2];"
        : "=r"(r0), "=r"(r1) : "r"(a));
}
__device__ __forceinline__ void cpa16(uint32_t dst, const void* src) {
    asm volatile("cp.async.cg.shared.global [%0], [%1], 16;" :: "r"(dst), "l"(src) : "memory");
}
#define CPA_COMMIT() asm volatile("cp.async.commit_group;" ::: "memory")
#define CPA_WAIT1()  asm volatile("cp.async.wait_group 1;" ::: "memory")
__device__ __forceinline__ uint32_t smem_to_u32(const void* p) {
    uint32_t a;
    asm("{ .reg .u64 t; cvta.to.shared.u64 t, %1; cvt.u32.u64 %0, t; }" : "=r"(a) : "l"(p));
    return a;
}
__device__ __forceinline__ uint32_t pack_bf16x2(float lo, float hi) {
    __nv_bfloat162 h = __floats2bfloat162_rn(lo, hi);
    return *(uint32_t*)&h;
}

// smem layout (bytes); padded A rows: 272 B (conflict-free ldmatrix)
#define KPB    272
#define ABUF(b) ((b) * 69632)          // each buf: hi @ +0 (34816), lo @ +34816
#define S_SAC2 139264                  // [8 warps][128 rows][20 floats] = 81920
#define S_TOTAL 221184

// ---------------- K5: HMMA split GEMM, W2 projection also on tensor pipe ----------------
__global__ __launch_bounds__(256) void k5_mma(
    const float* __restrict__ W1l, const float* __restrict__ W1r,
    const float* __restrict__ b1,
    const float* __restrict__ W2l, const float* __restrict__ W2r)
{
    extern __shared__ __align__(16) char smem[];
    uint32_t sbu = smem_to_u32(smem);
    int tid = threadIdx.x, wid = tid >> 5, lane = tid & 31;
    int gidq = lane >> 2, tig = lane & 3;

    // ---- stage B1-layer weights split into ABUF0 (temporary) ----
    for (int idx = tid; idx < 128 * 128; idx += 256) {
        int n = idx >> 7, k = idx & 127;
        float w = (k < 64) ? W1l[n * 64 + k] : W1r[n * 64 + (k - 64)];
        __nv_bfloat16 h = __float2bfloat16(w);
        __nv_bfloat16 l = __float2bfloat16(w - __bfloat162float(h));
        *(__nv_bfloat16*)(smem + n * KPB + k * 2) = h;
        *(__nv_bfloat16*)(smem + 34816 + n * KPB + k * 2) = l;
    }
    __syncthreads();

    // ---- hoist this warp's W1 B fragments (n-slice = wid*16 .. +16) ----
    uint32_t bh0[8][2], bh1[8][2], bl0[8][2], bl1[8][2];
    {
        int lsel = lane & 15;
        int nr = (lsel & 7);
        int kb8 = ((lsel >> 3) & 1) * 16;
#pragma unroll
        for (int ks = 0; ks < 8; ks++)
#pragma unroll
            for (int nt = 0; nt < 2; nt++) {
                uint32_t addr = sbu + (uint32_t)((wid * 16 + nt * 8 + nr) * KPB + ks * 32 + kb8);
                ldm_x2(bh0[ks][nt], bh1[ks][nt], addr);
                ldm_x2(bl0[ks][nt], bl1[ks][nt], addr + 34816);
            }
    }
    float b1g[2][2];
#pragma unroll
    for (int nt = 0; nt < 2; nt++)
#pragma unroll
        for (int e = 0; e < 2; e++)
            b1g[nt][e] = b1[wid * 16 + nt * 8 + tig * 2 + e];

    // ---- W2 projection B-fragments (register resident, split hi/res) ----
    // projection: P[16rows x 16n] = H[16 x 16k(local)] @ W2T[16k x 16n]
    // B frag (col-major KxN): b0 = (k=2tig..+1, n=gidq), b1 = (k=2tig+8..+9, n=gidq)
    uint32_t w2h_b0[2], w2h_b1[2], w2r_b0[2], w2r_b1[2];
    {
#pragma unroll
        for (int np = 0; np < 2; np++) {
            int n = np * 8 + gidq;   // output channel (0..15; >=12 padded 0)
            float wv[4];
#pragma unroll
            for (int kk = 0; kk < 4; kk++) {
                int c = wid * 16 + tig * 2 + (kk & 1) + (kk >> 1) * 8;
                float w = 0.f;
                if (n < 6)       w = W2l[n * 128 + c];
                else if (n < 12) w = W2r[(n - 6) * 128 + c];
                wv[kk] = w;
            }
            // hi parts
            __nv_bfloat162 h0 = __floats2bfloat162_rn(wv[0], wv[1]);
            __nv_bfloat162 h1 = __floats2bfloat162_rn(wv[2], wv[3]);
            w2h_b0[np] = *(uint32_t*)&h0;
            w2h_b1[np] = *(uint32_t*)&h1;
            // residuals
            w2r_b0[np] = pack_bf16x2(wv[0] - __bfloat162float(h0.x), wv[1] - __bfloat162float(h0.y));
            w2r_b1[np] = pack_bf16x2(wv[2] - __bfloat162float(h1.x), wv[3] - __bfloat162float(h1.y));
        }
    }
    __syncthreads();   // all frags read before cp.async overwrites ABUF0

    // ---- A staging (cp.async 16B chunks into padded rows) ----
    auto stageA = [&](int tileIdx, int buf) {
        int tb = min(tileIdx, TILES - 1) * 128;
        for (int c = tid; c < 2048; c += 256) {
            int row = c >> 4, wi = c & 15;
            int node = min(tb + row, TOT - 1);
            uint32_t dst = sbu + ABUF(buf) + row * KPB + wi * 16;
            cpa16(dst, g_ah + (size_t)node * 64 + wi * 4);
            cpa16(dst + 34816, g_al + (size_t)node * 64 + wi * 4);
        }
        CPA_COMMIT();
    };

    stageA(blockIdx.x, 0);
    int buf = 0;

    int arow_l = (lane & 7) + ((lane >> 3) & 1) * 8;
    int akb_l = (lane >> 4) * 16;

    for (int tile = blockIdx.x; tile < TILES; tile += gridDim.x) {
        stageA(tile + gridDim.x, buf ^ 1);
        CPA_WAIT1();
        __syncthreads();

        // ---- compute + tensor-pipe epilogue per mb (16 rows) ----
#pragma unroll 1
        for (int mb = 0; mb < 8; mb++) {
            float ahh[2][4], ahl[2][4], alh[2][4];
#pragma unroll
            for (int nt = 0; nt < 2; nt++)
#pragma unroll
                for (int e = 0; e < 4; e++) { ahh[nt][e] = 0.f; ahl[nt][e] = 0.f; alh[nt][e] = 0.f; }

#pragma unroll
            for (int ks = 0; ks < 8; ks++) {
                uint32_t abase = sbu + ABUF(buf) + (uint32_t)((mb * 16 + arow_l) * KPB + ks * 32 + akb_l);
                uint32_t a0, a1, a2, a3, c0, c1, c2, c3;
                ldm_x4(a0, a1, a2, a3, abase);
                ldm_x4(c0, c1, c2, c3, abase + 34816);
#pragma unroll
                for (int nt = 0; nt < 2; nt++) {
                    mma16816(ahh[nt], a0, a1, a2, a3, bh0[ks][nt], bh1[ks][nt]);
                    mma16816(ahl[nt], a0, a1, a2, a3, bl0[ks][nt], bl1[ks][nt]);
                    mma16816(alh[nt], c0, c1, c2, c3, bh0[ks][nt], bh1[ks][nt]);
                }
            }

            // h = relu(sum + bias), split to bf16 hi/lo as A-fragments of projection MMA
            float h[2][4];
#pragma unroll
            for (int nt = 0; nt < 2; nt++)
#pragma unroll
                for (int e = 0; e < 4; e++) {
                    float v = (ahh[nt][e] + ahl[nt][e]) + alh[nt][e] + b1g[nt][e & 1];
                    h[nt][e] = fmaxf(v, 0.f);
                }
            // A frag: a0=(row gidq, k=2tig..), a1=(row gidq+8, k=2tig..), a2/a3 = k+8 (nt=1 block)
            uint32_t pa0h, pa0l, pa1h, pa1l, pa2h, pa2l, pa3h, pa3l;
            split2(h[0][0], h[0][1], pa0h, pa0l);
            split2(h[0][2], h[0][3], pa1h, pa1l);
            split2(h[1][0], h[1][1], pa2h, pa2l);
            split2(h[1][2], h[1][3], pa3h, pa3l);

            float accP[2][4];
#pragma unroll
            for (int np = 0; np < 2; np++) {
#pragma unroll
                for (int e = 0; e < 4; e++) accP[np][e] = 0.f;
                mma16816(accP[np], pa0h, pa1h, pa2h, pa3h, w2h_b0[np], w2h_b1[np]);
                mma16816(accP[np], pa0l, pa1l, pa2l, pa3l, w2h_b0[np], w2h_b1[np]);
                mma16816(accP[np], pa0h, pa1h, pa2h, pa3h, w2r_b0[np], w2r_b1[np]);
            }

            // store P fragments to slab: C layout rows gidq/gidq+8, cols np*8 + 2tig..+1
            float* s0 = (float*)(smem + S_SAC2) + (size_t)(wid * 128 + mb * 16 + gidq) * 20;
#pragma unroll
            for (int np = 0; np < 2; np++) {
                *(float2*)(s0 + np * 8 + 2 * tig)            = make_float2(accP[np][0], accP[np][1]);
                *(float2*)(s0 + 8 * 20 + np * 8 + 2 * tig)   = make_float2(accP[np][2], accP[np][3]);
            }
        }
        __syncthreads();

        // ---- cross-warp reduce + writeout (threads 0..127 = rows) ----
        if (tid < 128) {
            int node = tile * 128 + tid;
            if (node < TOT) {
                float s[12];
#pragma unroll
                for (int j = 0; j < 12; j++) s[j] = 0.f;
#pragma unroll
                for (int w2 = 0; w2 < 8; w2++) {
                    const float* p = (const float*)(smem + S_SAC2) + (size_t)(w2 * 128 + tid) * 20;
                    float4 a = *(const float4*)p;
                    float4 b = *(const float4*)(p + 4);
                    float4 c = *(const float4*)(p + 8);
                    s[0] += a.x; s[1] += a.y; s[2] += a.z; s[3] += a.w;
                    s[4] += b.x; s[5] += b.y; s[6] += b.z; s[7] += b.w;
                    s[8] += c.x; s[9] += c.y; s[10] += c.z; s[11] += c.w;
                }
                float* gp = g_p + (size_t)node * 8;
                *(float4*)gp = make_float4(s[0], s[1], s[2], s[3]);
                *(float2*)(gp + 4) = make_float2(s[4], s[5]);
                float* gr = g_rr + (size_t)node * 8;
                *(float4*)gr = make_float4(s[6], s[7], s[8], s[9]);
                *(float2*)(gr + 4) = make_float2(s[10], s[11]);
            }
        }
        __syncthreads();
        buf ^= 1;
    }
}

// ---------------- K6: layer-2 aggregation + global max pool ----------------
#define K6_CHUNKS 157
__global__ void k6_layer2(const float* __restrict__ b2) {
    int t = blockIdx.x / K6_CHUNKS;
    int chunk = blockIdx.x % K6_CHUNKS;
    int i = chunk * 64 + (threadIdx.x >> 2);
    int q = threadIdx.x & 3;
    __shared__ unsigned zmax[6];
    if (threadIdx.x < 6) zmax[threadIdx.x] = 0u;
    __syncthreads();
    if (i < NN) {
        int node = t * NN + i;
        int deg = g_deg[node];
        int m = min(deg, CAP);
        const int* elist = g_slot + (size_t)node * CAP;
        int tb = t * NN;
        float s0 = 0, s1 = 0, s2 = 0, s3 = 0, s4 = 0, s5 = 0;
        for (int e = q; e < m; e += 4) {
            const float4* pp = (const float4*)(g_p + (size_t)(tb + elist[e]) * 8);
            float4 a = pp[0];
            float4 b = pp[1];
            s0 += a.x; s1 += a.y; s2 += a.z; s3 += a.w; s4 += b.x; s5 += b.y;
        }
#pragma unroll
        for (int o = 1; o <= 2; o <<= 1) {
            s0 += __shfl_xor_sync(0xffffffffu, s0, o);
            s1 += __shfl_xor_sync(0xffffffffu, s1, o);
            s2 += __shfl_xor_sync(0xffffffffu, s2, o);
            s3 += __shfl_xor_sync(0xffffffffu, s3, o);
            s4 += __shfl_xor_sync(0xffffffffu, s4, o);
            s5 += __shfl_xor_sync(0xffffffffu, s5, o);
        }
        if (q == 0) {
            float inv = 1.0f / (float)max(deg, 1);
            size_t base = (size_t)node * 8;
            atomicMax(&zmax[0], encf(s0 * inv + b2[0] + g_rr[base + 0]));
            atomicMax(&zmax[1], encf(s1 * inv + b2[1] + g_rr[base + 1]));
            atomicMax(&zmax[2], encf(s2 * inv + b2[2] + g_rr[base + 2]));
            atomicMax(&zmax[3], encf(s3 * inv + b2[3] + g_rr[base + 3]));
            atomicMax(&zmax[4], encf(s4 * inv + b2[4] + g_rr[base + 4]));
            atomicMax(&zmax[5], encf(s5 * inv + b2[5] + g_rr[base + 5]));
        }
    }
    __syncthreads();
    if (threadIdx.x < 6) atomicMax(&g_zenc[t * 8 + threadIdx.x], zmax[threadIdx.x]);
}

// ---------------- K7: GRU + NCE + outputs ----------------
__global__ void k7_final(const float* __restrict__ wih,
                         const float* __restrict__ bih,
                         const float* __restrict__ bhh,
                         float* __restrict__ out, int out_size)
{
    __shared__ float z[T * 6];
    __shared__ float gout[30 * 6];
    __shared__ float redf[256];
    __shared__ int   redi[256];
    int tid = threadIdx.x;
    for (int idx = tid; idx < T * 6; idx += 256)
        z[idx] = decf(g_zenc[(idx / 6) * 8 + (idx % 6)]);
    __syncthreads();
    if (tid < 180) {
        int t = tid / 6, j = tid % 6;
        float ar = 0.f, au = 0.f, an = 0.f;
#pragma unroll
        for (int d = 0; d < 6; d++) {
            float zv = z[t * 6 + d];
            ar += zv * wih[(0 + j) * 6 + d];
            au += zv * wih[(6 + j) * 6 + d];
            an += zv * wih[(12 + j) * 6 + d];
        }
        float r = 1.f / (1.f + expf(-(ar + bih[j]      + bhh[j])));
        float u = 1.f / (1.f + expf(-(au + bih[6 + j]  + bhh[6 + j])));
        float n = tanhf(an + bih[12 + j] + r * bhh[12 + j]);
        gout[tid] = (1.f - u) * n;
    }
    __syncthreads();
    float lnce = 0.f; int lc = 0;
    if (tid < 240) {
        int tp = tid / 12;
        int ii = tid % 12 + 1;
        int t = 10 + tp;
        const int joff[8] = {0, 11, 12, 13, 14, 15, 16, 17};
        float lg[8];
#pragma unroll
        for (int s = 0; s < 8; s++) {
            int idx = t + ii + joff[s];
            float d = 0.f;
#pragma unroll
            for (int c = 0; c < 6; c++) d += z[idx * 6 + c] * gout[t * 6 + c];
            lg[s] = d;
        }
        float m = lg[0];
#pragma unroll
        for (int s = 1; s < 8; s++) m = fmaxf(m, lg[s]);
        float se = 0.f;
#pragma unroll
        for (int s = 0; s < 8; s++) se += expf(lg[s] - m);
        lnce = lg[0] - m - logf(se);
        bool ok = true;
#pragma unroll
        for (int s = 1; s < 8; s++) if (lg[s] > lg[0]) ok = false;
        lc = ok ? 1 : 0;
    }
    redf[tid] = lnce; redi[tid] = lc;
    __syncthreads();
    for (int o = 128; o > 0; o >>= 1) {
        if (tid < o) { redf[tid] += redf[tid + o]; redi[tid] += redi[tid + o]; }
        __syncthreads();
    }
    if (tid == 0) {
        if (out_size > 0) out[0] = redf[0] / (-240.0f);
        if (out_size > 1) out[1] = (float)redi[0] / 240.0f;
    }
    if (tid < 180 && (2 + tid) < out_size) out[2 + tid] = gout[tid];
    for (int idx = 182 + tid; idx < out_size; idx += 256) out[idx] = 0.f;
}

// ---------------- launch ----------------
extern "C" void kernel_launch(void* const* d_in, const int* in_sizes, int n_in,
                              void* d_out, int out_size)
{
    const float* x   = (const float*)d_in[0];
    const int*   ei  = (const int*)  d_in[1];
    const float* W1l = (const float*)d_in[2];
    const float* W1r = (const float*)d_in[3];
    const float* b1  = (const float*)d_in[4];
    const float* W2l = (const float*)d_in[5];
    const float* W2r = (const float*)d_in[6];
    const float* b2  = (const float*)d_in[7];
    const float* wih = (const float*)d_in[8];
    const float* bih = (const float*)d_in[10];
    const float* bhh = (const float*)d_in[11];
    float* out = (float*)d_out;

    cudaFuncSetAttribute(k5_mma, cudaFuncAttributeMaxDynamicSharedMemorySize, S_TOTAL);

    k0_init <<<(TOT + 255) / 256, 256>>>();
    k1_build<<<(T * (EE / 8) + 255) / 256, 256>>>(ei);
    k4a_agg <<<(TOT * 32 + 255) / 256, 256>>>(x);
    k5_mma  <<<148, 256, S_TOTAL>>>(W1l, W1r, b1, W2l, W2r);
    k6_layer2<<<T * K6_CHUNKS, 256>>>(b2);
    k7_final<<<1, 256>>>(wih, bih, bhh, out, out_size);
}

// round 12
// speedup vs baseline: 1.1664x; 1.0336x over previous
#include <cuda_runtime.h>
#include <cuda_bf16.h>
#include <cstdint>
#include <cstddef>
#include <math.h>

#define T    60
#define NN   10000
#define EE   160000
#define INC  64
#define CAP  64
#define TOT  (T * NN)
#define TILES ((TOT + 127) / 128)

// ---------------- scratch ----------------
__device__ int      g_deg [TOT];
__device__ int      g_slot[(size_t)TOT * CAP];
__device__ uint32_t g_ah[(size_t)TOT * 64];   // bf16x2 rows: [mean(0..63)|x(64..127)] hi
__device__ uint32_t g_al[(size_t)TOT * 64];   // residual lo
__device__ float    g_p   [(size_t)TOT * 8];
__device__ float    g_rr  [(size_t)TOT * 8];
__device__ unsigned g_zenc[T * 8];

__device__ __forceinline__ unsigned encf(float f) {
    unsigned u = __float_as_uint(f);
    return (u & 0x80000000u) ? ~u : (u | 0x80000000u);
}
__device__ __forceinline__ float decf(unsigned u) {
    return (u & 0x80000000u) ? __uint_as_float(u & 0x7fffffffu) : __uint_as_float(~u);
}

// ---------------- K0: init ----------------
__global__ void k0_init() {
    int idx = blockIdx.x * blockDim.x + threadIdx.x;
    if (idx < TOT) g_deg[idx] = 0;
    if (idx < T * 8) g_zenc[idx] = 0u;
}

// ---------------- K1: single-pass bucketed CSR build (8 edges/thread) ----------------
__global__ void k1_build(const int* __restrict__ ei) {
    int q = blockIdx.x * blockDim.x + threadIdx.x;
    if (q >= T * (EE / 8)) return;
    int t = q / (EE / 8);
    int e = (q - t * (EE / 8)) * 8;
    const int* sp = ei + (size_t)t * 2 * EE + e;
    int4 sva = *(const int4*)sp;
    int4 svb = *(const int4*)(sp + 4);
    int4 dva = *(const int4*)(sp + EE);
    int4 dvb = *(const int4*)(sp + EE + 4);
    int tb = t * NN;
    int d0 = tb + dva.x, d1 = tb + dva.y, d2 = tb + dva.z, d3 = tb + dva.w;
    int d4 = tb + dvb.x, d5 = tb + dvb.y, d6 = tb + dvb.z, d7 = tb + dvb.w;
    int p0 = atomicAdd(&g_deg[d0], 1);
    int p1 = atomicAdd(&g_deg[d1], 1);
    int p2 = atomicAdd(&g_deg[d2], 1);
    int p3 = atomicAdd(&g_deg[d3], 1);
    int p4 = atomicAdd(&g_deg[d4], 1);
    int p5 = atomicAdd(&g_deg[d5], 1);
    int p6 = atomicAdd(&g_deg[d6], 1);
    int p7 = atomicAdd(&g_deg[d7], 1);
    if (p0 < CAP) g_slot[(size_t)d0 * CAP + p0] = sva.x;
    if (p1 < CAP) g_slot[(size_t)d1 * CAP + p1] = sva.y;
    if (p2 < CAP) g_slot[(size_t)d2 * CAP + p2] = sva.z;
    if (p3 < CAP) g_slot[(size_t)d3 * CAP + p3] = sva.w;
    if (p4 < CAP) g_slot[(size_t)d4 * CAP + p4] = svb.x;
    if (p5 < CAP) g_slot[(size_t)d5 * CAP + p5] = svb.y;
    if (p6 < CAP) g_slot[(size_t)d6 * CAP + p6] = svb.z;
    if (p7 < CAP) g_slot[(size_t)d7 * CAP + p7] = svb.w;
}

// ---------------- bf16 split helpers ----------------
__device__ __forceinline__ void split2(float a, float b, uint32_t& hi, uint32_t& lo) {
    __nv_bfloat162 h = __floats2bfloat162_rn(a, b);
    float ra = a - __bfloat162float(h.x);
    float rb = b - __bfloat162float(h.y);
    __nv_bfloat162 l = __floats2bfloat162_rn(ra, rb);
    hi = *(uint32_t*)&h;
    lo = *(uint32_t*)&l;
}

// ---------------- K4a: mean aggregation + split-bf16 A-row emit (warp/node) ----------------
__global__ void k4a_agg(const float* __restrict__ x) {
    int w = (blockIdx.x * blockDim.x + threadIdx.x) >> 5;
    int lane = threadIdx.x & 31;
    if (w >= TOT) return;
    int node = w;
    int t = node / NN;
    int deg = g_deg[node];
    int m = min(deg, CAP);
    const int* elist = g_slot + (size_t)node * CAP;
    const float* xt = x + (size_t)t * NN * INC;
    float sx = 0.f, sy = 0.f;
    int e = 0;
    for (; e + 8 <= m; e += 8) {
        int s0 = elist[e+0], s1 = elist[e+1], s2 = elist[e+2], s3 = elist[e+3];
        int s4 = elist[e+4], s5 = elist[e+5], s6 = elist[e+6], s7 = elist[e+7];
        float2 v0 = ((const float2*)(xt + (size_t)s0 * INC))[lane];
        float2 v1 = ((const float2*)(xt + (size_t)s1 * INC))[lane];
        float2 v2 = ((const float2*)(xt + (size_t)s2 * INC))[lane];
        float2 v3 = ((const float2*)(xt + (size_t)s3 * INC))[lane];
        float2 v4 = ((const float2*)(xt + (size_t)s4 * INC))[lane];
        float2 v5 = ((const float2*)(xt + (size_t)s5 * INC))[lane];
        float2 v6 = ((const float2*)(xt + (size_t)s6 * INC))[lane];
        float2 v7 = ((const float2*)(xt + (size_t)s7 * INC))[lane];
        sx += ((v0.x + v1.x) + (v2.x + v3.x)) + ((v4.x + v5.x) + (v6.x + v7.x));
        sy += ((v0.y + v1.y) + (v2.y + v3.y)) + ((v4.y + v5.y) + (v6.y + v7.y));
    }
    for (; e < m; e++) {
        int s0 = elist[e];
        float2 v0 = ((const float2*)(xt + (size_t)s0 * INC))[lane];
        sx += v0.x; sy += v0.y;
    }
    float inv = 1.0f / (float)max(deg, 1);
    uint32_t hi, lo;
    split2(sx * inv, sy * inv, hi, lo);
    g_ah[(size_t)node * 64 + lane] = hi;
    g_al[(size_t)node * 64 + lane] = lo;
    float2 xv = ((const float2*)(x + (size_t)node * INC))[lane];
    split2(xv.x, xv.y, hi, lo);
    g_ah[(size_t)node * 64 + 32 + lane] = hi;
    g_al[(size_t)node * 64 + 32 + lane] = lo;
}

// ---------------- mma / ldmatrix / cp.async helpers ----------------
__device__ __forceinline__ void mma16816(float* c,
    uint32_t a0, uint32_t a1, uint32_t a2, uint32_t a3, uint32_t b0, uint32_t b1)
{
    asm volatile(
        "mma.sync.aligned.m16n8k16.row.col.f32.bf16.bf16.f32 "
        "{%0,%1,%2,%3}, {%4,%5,%6,%7}, {%8,%9}, {%0,%1,%2,%3};"
        : "+f"(c[0]), "+f"(c[1]), "+f"(c[2]), "+f"(c[3])
        : "r"(a0), "r"(a1), "r"(a2), "r"(a3), "r"(b0), "r"(b1));
}
__device__ __forceinline__ void ldm_x4(uint32_t& r0, uint32_t& r1, uint32_t& r2, uint32_t& r3, uint32_t a) {
    asm volatile("ldmatrix.sync.aligned.m8n8.x4.shared.b16 {%0,%1,%2,%3}, [%4];"
        : "=r"(r0), "=r"(r1), "=r"(r2), "=r"(r3) : "r"(a));
}
__device__ __forceinline__ void ldm_x2(uint32_t& r0, uint32_t& r1, uint32_t a) {
    asm volatile("ldmatrix.sync.aligned.m8n8.x2.shared.b16 {%0,%1}, [%2];"
        : "=r"(r0), "=r"(r1) : "r"(a));
}
__device__ __forceinline__ void cpa16(uint32_t dst, const void* src) {
    asm volatile("cp.async.cg.shared.global [%0], [%1], 16;" :: "r"(dst), "l"(src) : "memory");
}
#define CPA_COMMIT() asm volatile("cp.async.commit_group;" ::: "memory")
#define CPA_WAIT1()  asm volatile("cp.async.wait_group 1;" ::: "memory")
__device__ __forceinline__ uint32_t smem_to_u32(const void* p) {
    uint32_t a;
    asm("{ .reg .u64 t; cvta.to.shared.u64 t, %1; cvt.u32.u64 %0, t; }" : "=r"(a) : "l"(p));
    return a;
}
__device__ __forceinline__ uint32_t pack_bf16x2(float lo, float hi) {
    __nv_bfloat162 h = __floats2bfloat162_rn(lo, hi);
    return *(uint32_t*)&h;
}

// smem layout (bytes); padded A rows: 272 B (conflict-free ldmatrix)
#define KPB    272
#define ABUF(b) ((b) * 69632)          // each buf: hi @ +0 (34816), lo @ +34816
#define S_SAC2 139264                  // [8 n-groups][128 rows][20 floats] = 81920
#define S_TOTAL 221184

#define NTHR 512

// ---------------- K5: HMMA split GEMM, 16 warps = 8 n-groups x 2 m-groups ----------------
__global__ __launch_bounds__(NTHR) void k5_mma(
    const float* __restrict__ W1l, const float* __restrict__ W1r,
    const float* __restrict__ b1,
    const float* __restrict__ W2l, const float* __restrict__ W2r)
{
    extern __shared__ __align__(16) char smem[];
    uint32_t sbu = smem_to_u32(smem);
    int tid = threadIdx.x, wid = tid >> 5, lane = tid & 31;
    int ng = wid & 7;          // n-group: cols ng*16..+16
    int mg = wid >> 3;         // m-group: mb blocks mg*4..+4
    int gidq = lane >> 2, tig = lane & 3;

    // ---- stage B1-layer weights split into ABUF0 (temporary) ----
    for (int idx = tid; idx < 128 * 128; idx += NTHR) {
        int n = idx >> 7, k = idx & 127;
        float w = (k < 64) ? W1l[n * 64 + k] : W1r[n * 64 + (k - 64)];
        __nv_bfloat16 h = __float2bfloat16(w);
        __nv_bfloat16 l = __float2bfloat16(w - __bfloat162float(h));
        *(__nv_bfloat16*)(smem + n * KPB + k * 2) = h;
        *(__nv_bfloat16*)(smem + 34816 + n * KPB + k * 2) = l;
    }
    __syncthreads();

    // ---- hoist this warp's W1 B fragments (n-slice = ng*16 .. +16) ----
    uint32_t bh0[8][2], bh1[8][2], bl0[8][2], bl1[8][2];
    {
        int lsel = lane & 15;
        int nr = (lsel & 7);
        int kb8 = ((lsel >> 3) & 1) * 16;
#pragma unroll
        for (int ks = 0; ks < 8; ks++)
#pragma unroll
            for (int nt = 0; nt < 2; nt++) {
                uint32_t addr = sbu + (uint32_t)((ng * 16 + nt * 8 + nr) * KPB + ks * 32 + kb8);
                ldm_x2(bh0[ks][nt], bh1[ks][nt], addr);
                ldm_x2(bl0[ks][nt], bl1[ks][nt], addr + 34816);
            }
    }
    float b1g[2][2];
#pragma unroll
    for (int nt = 0; nt < 2; nt++)
#pragma unroll
        for (int e = 0; e < 2; e++)
            b1g[nt][e] = b1[ng * 16 + nt * 8 + tig * 2 + e];

    // ---- W2 projection B-fragments (register resident, split hi/res) ----
    uint32_t w2h_b0[2], w2h_b1[2], w2r_b0[2], w2r_b1[2];
    {
#pragma unroll
        for (int np = 0; np < 2; np++) {
            int n = np * 8 + gidq;   // output channel (0..15; >=12 padded 0)
            float wv[4];
#pragma unroll
            for (int kk = 0; kk < 4; kk++) {
                int c = ng * 16 + tig * 2 + (kk & 1) + (kk >> 1) * 8;
                float w = 0.f;
                if (n < 6)       w = W2l[n * 128 + c];
                else if (n < 12) w = W2r[(n - 6) * 128 + c];
                wv[kk] = w;
            }
            __nv_bfloat162 h0 = __floats2bfloat162_rn(wv[0], wv[1]);
            __nv_bfloat162 h1 = __floats2bfloat162_rn(wv[2], wv[3]);
            w2h_b0[np] = *(uint32_t*)&h0;
            w2h_b1[np] = *(uint32_t*)&h1;
            w2r_b0[np] = pack_bf16x2(wv[0] - __bfloat162float(h0.x), wv[1] - __bfloat162float(h0.y));
            w2r_b1[np] = pack_bf16x2(wv[2] - __bfloat162float(h1.x), wv[3] - __bfloat162float(h1.y));
        }
    }
    __syncthreads();   // all frags read before cp.async overwrites ABUF0

    // ---- A staging (cp.async 16B chunks into padded rows) ----
    auto stageA = [&](int tileIdx, int buf) {
        int tb = min(tileIdx, TILES - 1) * 128;
        for (int c = tid; c < 2048; c += NTHR) {
            int row = c >> 4, wi = c & 15;
            int node = min(tb + row, TOT - 1);
            uint32_t dst = sbu + ABUF(buf) + row * KPB + wi * 16;
            cpa16(dst, g_ah + (size_t)node * 64 + wi * 4);
            cpa16(dst + 34816, g_al + (size_t)node * 64 + wi * 4);
        }
        CPA_COMMIT();
    };

    stageA(blockIdx.x, 0);
    int buf = 0;

    int arow_l = (lane & 7) + ((lane >> 3) & 1) * 8;
    int akb_l = (lane >> 4) * 16;

    for (int tile = blockIdx.x; tile < TILES; tile += gridDim.x) {
        stageA(tile + gridDim.x, buf ^ 1);
        CPA_WAIT1();
        __syncthreads();

        // ---- compute + tensor-pipe epilogue: this warp's 4 mb blocks ----
#pragma unroll 1
        for (int mbi = 0; mbi < 4; mbi++) {
            int mb = mg * 4 + mbi;
            float ahh[2][4], ahl[2][4], alh[2][4];
#pragma unroll
            for (int nt = 0; nt < 2; nt++)
#pragma unroll
                for (int e = 0; e < 4; e++) { ahh[nt][e] = 0.f; ahl[nt][e] = 0.f; alh[nt][e] = 0.f; }

#pragma unroll
            for (int ks = 0; ks < 8; ks++) {
                uint32_t abase = sbu + ABUF(buf) + (uint32_t)((mb * 16 + arow_l) * KPB + ks * 32 + akb_l);
                uint32_t a0, a1, a2, a3, c0, c1, c2, c3;
                ldm_x4(a0, a1, a2, a3, abase);
                ldm_x4(c0, c1, c2, c3, abase + 34816);
#pragma unroll
                for (int nt = 0; nt < 2; nt++) {
                    mma16816(ahh[nt], a0, a1, a2, a3, bh0[ks][nt], bh1[ks][nt]);
                    mma16816(ahl[nt], a0, a1, a2, a3, bl0[ks][nt], bl1[ks][nt]);
                    mma16816(alh[nt], c0, c1, c2, c3, bh0[ks][nt], bh1[ks][nt]);
                }
            }

            // h = relu(sum + bias), split to bf16 hi/lo as A-fragments of projection MMA
            float h[2][4];
#pragma unroll
            for (int nt = 0; nt < 2; nt++)
#pragma unroll
                for (int e = 0; e < 4; e++) {
                    float v = (ahh[nt][e] + ahl[nt][e]) + alh[nt][e] + b1g[nt][e & 1];
                    h[nt][e] = fmaxf(v, 0.f);
                }
            uint32_t pa0h, pa0l, pa1h, pa1l, pa2h, pa2l, pa3h, pa3l;
            split2(h[0][0], h[0][1], pa0h, pa0l);
            split2(h[0][2], h[0][3], pa1h, pa1l);
            split2(h[1][0], h[1][1], pa2h, pa2l);
            split2(h[1][2], h[1][3], pa3h, pa3l);

            float accP[2][4];
#pragma unroll
            for (int np = 0; np < 2; np++) {
#pragma unroll
                for (int e = 0; e < 4; e++) accP[np][e] = 0.f;
                mma16816(accP[np], pa0h, pa1h, pa2h, pa3h, w2h_b0[np], w2h_b1[np]);
                mma16816(accP[np], pa0l, pa1l, pa2l, pa3l, w2h_b0[np], w2h_b1[np]);
                mma16816(accP[np], pa0h, pa1h, pa2h, pa3h, w2r_b0[np], w2r_b1[np]);
            }

            // store P fragments to slab (keyed by n-group; m rows disjoint across mg)
            float* s0 = (float*)(smem + S_SAC2) + (size_t)(ng * 128 + mb * 16 + gidq) * 20;
#pragma unroll
            for (int np = 0; np < 2; np++) {
                *(float2*)(s0 + np * 8 + 2 * tig)            = make_float2(accP[np][0], accP[np][1]);
                *(float2*)(s0 + 8 * 20 + np * 8 + 2 * tig)   = make_float2(accP[np][2], accP[np][3]);
            }
        }
        __syncthreads();

        // ---- cross-n-group reduce + writeout (threads 0..127 = rows) ----
        if (tid < 128) {
            int node = tile * 128 + tid;
            if (node < TOT) {
                float s[12];
#pragma unroll
                for (int j = 0; j < 12; j++) s[j] = 0.f;
#pragma unroll
                for (int w2 = 0; w2 < 8; w2++) {
                    const float* p = (const float*)(smem + S_SAC2) + (size_t)(w2 * 128 + tid) * 20;
                    float4 a = *(const float4*)p;
                    float4 b = *(const float4*)(p + 4);
                    float4 c = *(const float4*)(p + 8);
                    s[0] += a.x; s[1] += a.y; s[2] += a.z; s[3] += a.w;
                    s[4] += b.x; s[5] += b.y; s[6] += b.z; s[7] += b.w;
                    s[8] += c.x; s[9] += c.y; s[10] += c.z; s[11] += c.w;
                }
                float* gp = g_p + (size_t)node * 8;
                *(float4*)gp = make_float4(s[0], s[1], s[2], s[3]);
                *(float2*)(gp + 4) = make_float2(s[4], s[5]);
                float* gr = g_rr + (size_t)node * 8;
                *(float4*)gr = make_float4(s[6], s[7], s[8], s[9]);
                *(float2*)(gr + 4) = make_float2(s[10], s[11]);
            }
        }
        __syncthreads();
        buf ^= 1;
    }
}

// ---------------- K6: layer-2 aggregation + global max pool ----------------
#define K6_CHUNKS 157
__global__ void k6_layer2(const float* __restrict__ b2) {
    int t = blockIdx.x / K6_CHUNKS;
    int chunk = blockIdx.x % K6_CHUNKS;
    int i = chunk * 64 + (threadIdx.x >> 2);
    int q = threadIdx.x & 3;
    __shared__ unsigned zmax[6];
    if (threadIdx.x < 6) zmax[threadIdx.x] = 0u;
    __syncthreads();
    if (i < NN) {
        int node = t * NN + i;
        int deg = g_deg[node];
        int m = min(deg, CAP);
        const int* elist = g_slot + (size_t)node * CAP;
        int tb = t * NN;
        float s0 = 0, s1 = 0, s2 = 0, s3 = 0, s4 = 0, s5 = 0;
        for (int e = q; e < m; e += 4) {
            const float4* pp = (const float4*)(g_p + (size_t)(tb + elist[e]) * 8);
            float4 a = pp[0];
            float4 b = pp[1];
            s0 += a.x; s1 += a.y; s2 += a.z; s3 += a.w; s4 += b.x; s5 += b.y;
        }
#pragma unroll
        for (int o = 1; o <= 2; o <<= 1) {
            s0 += __shfl_xor_sync(0xffffffffu, s0, o);
            s1 += __shfl_xor_sync(0xffffffffu, s1, o);
            s2 += __shfl_xor_sync(0xffffffffu, s2, o);
            s3 += __shfl_xor_sync(0xffffffffu, s3, o);
            s4 += __shfl_xor_sync(0xffffffffu, s4, o);
            s5 += __shfl_xor_sync(0xffffffffu, s5, o);
        }
        if (q == 0) {
            float inv = 1.0f / (float)max(deg, 1);
            size_t base = (size_t)node * 8;
            atomicMax(&zmax[0], encf(s0 * inv + b2[0] + g_rr[base + 0]));
            atomicMax(&zmax[1], encf(s1 * inv + b2[1] + g_rr[base + 1]));
            atomicMax(&zmax[2], encf(s2 * inv + b2[2] + g_rr[base + 2]));
            atomicMax(&zmax[3], encf(s3 * inv + b2[3] + g_rr[base + 3]));
            atomicMax(&zmax[4], encf(s4 * inv + b2[4] + g_rr[base + 4]));
            atomicMax(&zmax[5], encf(s5 * inv + b2[5] + g_rr[base + 5]));
        }
    }
    __syncthreads();
    if (threadIdx.x < 6) atomicMax(&g_zenc[t * 8 + threadIdx.x], zmax[threadIdx.x]);
}

// ---------------- K7: GRU + NCE + outputs ----------------
__global__ void k7_final(const float* __restrict__ wih,
                         const float* __restrict__ bih,
                         const float* __restrict__ bhh,
                         float* __restrict__ out, int out_size)
{
    __shared__ float z[T * 6];
    __shared__ float gout[30 * 6];
    __shared__ float redf[256];
    __shared__ int   redi[256];
    int tid = threadIdx.x;
    for (int idx = tid; idx < T * 6; idx += 256)
        z[idx] = decf(g_zenc[(idx / 6) * 8 + (idx % 6)]);
    __syncthreads();
    if (tid < 180) {
        int t = tid / 6, j = tid % 6;
        float ar = 0.f, au = 0.f, an = 0.f;
#pragma unroll
        for (int d = 0; d < 6; d++) {
            float zv = z[t * 6 + d];
            ar += zv * wih[(0 + j) * 6 + d];
            au += zv * wih[(6 + j) * 6 + d];
            an += zv * wih[(12 + j) * 6 + d];
        }
        float r = 1.f / (1.f + expf(-(ar + bih[j]      + bhh[j])));
        float u = 1.f / (1.f + expf(-(au + bih[6 + j]  + bhh[6 + j])));
        float n = tanhf(an + bih[12 + j] + r * bhh[12 + j]);
        gout[tid] = (1.f - u) * n;
    }
    __syncthreads();
    float lnce = 0.f; int lc = 0;
    if (tid < 240) {
        int tp = tid / 12;
        int ii = tid % 12 + 1;
        int t = 10 + tp;
        const int joff[8] = {0, 11, 12, 13, 14, 15, 16, 17};
        float lg[8];
#pragma unroll
        for (int s = 0; s < 8; s++) {
            int idx = t + ii + joff[s];
            float d = 0.f;
#pragma unroll
            for (int c = 0; c < 6; c++) d += z[idx * 6 + c] * gout[t * 6 + c];
            lg[s] = d;
        }
        float m = lg[0];
#pragma unroll
        for (int s = 1; s < 8; s++) m = fmaxf(m, lg[s]);
        float se = 0.f;
#pragma unroll
        for (int s = 0; s < 8; s++) se += expf(lg[s] - m);
        lnce = lg[0] - m - logf(se);
        bool ok = true;
#pragma unroll
        for (int s = 1; s < 8; s++) if (lg[s] > lg[0]) ok = false;
        lc = ok ? 1 : 0;
    }
    redf[tid] = lnce; redi[tid] = lc;
    __syncthreads();
    for (int o = 128; o > 0; o >>= 1) {
        if (tid < o) { redf[tid] += redf[tid + o]; redi[tid] += redi[tid + o]; }
        __syncthreads();
    }
    if (tid == 0) {
        if (out_size > 0) out[0] = redf[0] / (-240.0f);
        if (out_size > 1) out[1] = (float)redi[0] / 240.0f;
    }
    if (tid < 180 && (2 + tid) < out_size) out[2 + tid] = gout[tid];
    for (int idx = 182 + tid; idx < out_size; idx += 256) out[idx] = 0.f;
}

// ---------------- launch ----------------
extern "C" void kernel_launch(void* const* d_in, const int* in_sizes, int n_in,
                              void* d_out, int out_size)
{
    const float* x   = (const float*)d_in[0];
    const int*   ei  = (const int*)  d_in[1];
    const float* W1l = (const float*)d_in[2];
    const float* W1r = (const float*)d_in[3];
    const float* b1  = (const float*)d_in[4];
    const float* W2l = (const float*)d_in[5];
    const float* W2r = (const float*)d_in[6];
    const float* b2  = (const float*)d_in[7];
    const float* wih = (const float*)d_in[8];
    const float* bih = (const float*)d_in[10];
    const float* bhh = (const float*)d_in[11];
    float* out = (float*)d_out;

    cudaFuncSetAttribute(k5_mma, cudaFuncAttributeMaxDynamicSharedMemorySize, S_TOTAL);

    k0_init <<<(TOT + 255) / 256, 256>>>();
    k1_build<<<(T * (EE / 8) + 255) / 256, 256>>>(ei);
    k4a_agg <<<(TOT * 32 + 255) / 256, 256>>>(x);
    k5_mma  <<<148, NTHR, S_TOTAL>>>(W1l, W1r, b1, W2l, W2r);
    k6_layer2<<<T * K6_CHUNKS, 256>>>(b2);
    k7_final<<<1, 256>>>(wih, bih, bhh, out, out_size);
}